// round 13
// baseline (speedup 1.0000x reference)
#include <cuda_runtime.h>
#include <math.h>

#define B_TOTAL 65536
#define NBLK (B_TOTAL / 32)
#define NL 7

typedef unsigned long long u64;

// ---- scratch (static device globals) ----
__device__ __align__(16) float g_traces_blk[(size_t)B_TOTAL * 224];   // [blk][c][d][32]
__device__ __align__(16) float g_gates_T[(size_t)NL * B_TOTAL];       // [line][b]
__device__ __align__(16) float g_z_blk[(size_t)B_TOTAL * 98];         // [blk][98][32]

__constant__ int FSRC[21] = {0,1,2, 0,3,4, 0,5,6, 1,3,5, 1,4,6, 2,3,6, 2,4,5};
__constant__ int FPAR[21] = {1,2,0, 3,4,0, 5,6,0, 3,5,1, 4,6,1, 3,6,2, 4,5,2};

__device__ __forceinline__ u64 pack2(float x, float y) {
    u64 r; asm("mov.b64 %0, {%1,%2};" : "=l"(r) : "f"(x), "f"(y)); return r;
}
__device__ __forceinline__ float2 unpack2(u64 v) {
    float2 r; asm("mov.b64 {%0,%1}, %2;" : "=f"(r.x), "=f"(r.y) : "l"(v)); return r;
}
__device__ __forceinline__ u64 dup2(float x) { return pack2(x, x); }
__device__ __forceinline__ u64 ffma2(u64 a, u64 b, u64 c) {
    u64 d; asm("fma.rn.f32x2 %0, %1, %2, %3;" : "=l"(d) : "l"(a), "l"(b), "l"(c)); return d;
}
__device__ __forceinline__ u64 add2(u64 a, u64 b) {
    u64 d; asm("add.rn.f32x2 %0, %1, %2;" : "=l"(d) : "l"(a), "l"(b)); return d;
}
__device__ __forceinline__ u64 mul2(u64 a, u64 b) {
    u64 d; asm("mul.rn.f32x2 %0, %1, %2;" : "=l"(d) : "l"(a), "l"(b)); return d;
}

__device__ __forceinline__ float fast_sigmoid(float x) {
    return __fdividef(1.0f, 1.0f + __expf(-x));
}

__device__ __forceinline__ float colony_act(int c, float x) {
    switch (c) {
        case 0: return fmaxf(x, 0.0f);
        case 1: { float e = __expf(2.0f * x); return 1.0f - __fdividef(2.0f, e + 1.0f); }
        case 2: return 0.5f * x * (1.0f + erff(x * 0.7071067811865476f));
        case 3: return x * fast_sigmoid(x);
        case 4: return fmaxf(x, 0.0f) + log1pf(__expf(-fabsf(x)));
        case 5: return fast_sigmoid(x);
        default: return fminf(fmaxf(x, -1.0f), 1.0f);
    }
}

// ============================================================================
// Kernel Z: transpose z [B][98] -> z_blk [blk][98][32]  (pure bandwidth)
// ============================================================================
__global__ void __launch_bounds__(256, 4)
colony_kz(const float* __restrict__ z)
{
    __shared__ float tile[32 * 99];
    const int blk = blockIdx.x;
    const float* src = z + (size_t)blk * 3136;
    for (int idx = threadIdx.x; idx < 3136; idx += 256) {
        int b = idx / 98, q = idx % 98;
        tile[b * 99 + q] = src[idx];
    }
    __syncthreads();
    float* dst = g_z_blk + (size_t)blk * 3136;
    for (int idx = threadIdx.x; idx < 3136; idx += 256) {
        int q = idx >> 5, bb = idx & 31;
        dst[idx] = tile[bb * 99 + q];
    }
}

// ============================================================================
// Kernel 1: lane = batch; 12 warps (rows shrunk to 76 floats/lane).
// ============================================================================
#define K1_WARPS 12
#define K1_THREADS (K1_WARPS * 32)
#define K1_ROW 76    // h [0,64) | conf [64,71) | pad ; 76 = 4*19 -> conflict-free float4
#define K1_WSZ (27344 + K1_WARPS * 32 * K1_ROW)
#define K1_SMEM (K1_WSZ * 4)

__global__ void __launch_bounds__(K1_THREADS, 1)
colony_k1(const float* __restrict__ gen_W1, const float* __restrict__ gen_b1,
          const float* __restrict__ gen_g,  const float* __restrict__ gen_be,
          const float* __restrict__ gen_W2, const float* __restrict__ gen_b2,
          const float* __restrict__ cf_W1,  const float* __restrict__ cf_b1,
          const float* __restrict__ cf_W2,  const float* __restrict__ cf_b2,
          const float* __restrict__ gw,     const float* __restrict__ gb,
          float* __restrict__ out_conf)
{
    extern __shared__ __align__(16) float sm[];
    float* sW1  = sm;            // 6272  [7][14][64]
    float* sb1  = sW1  + 6272;   // 448
    float* sg   = sb1  + 448;    // 448
    float* sbe  = sg   + 448;    // 448
    float* sW2  = sbe  + 448;    // 14336 [7][64][32]
    float* sb2  = sW2  + 14336;  // 224
    float* scW1 = sb2  + 224;    // 3136  [7][14][32]
    float* scb1 = scW1 + 3136;   // 224
    float* scW2 = scb1 + 224;    // 224
    float* scb2 = scW2 + 224;    // 8
    float* sgWT = scb2 + 8;      // 1568  transposed [7][224]
    float* sgb  = sgWT + 1568;   // 8
    float* rows = sgb  + 8;

    const int tid = threadIdx.x;
    for (int i = tid; i < 6272;  i += blockDim.x) sW1[i]  = gen_W1[i];
    for (int i = tid; i < 448;   i += blockDim.x) sb1[i]  = gen_b1[i];
    for (int i = tid; i < 448;   i += blockDim.x) sg[i]   = gen_g[i];
    for (int i = tid; i < 448;   i += blockDim.x) sbe[i]  = gen_be[i];
    for (int i = tid; i < 14336; i += blockDim.x) sW2[i]  = gen_W2[i];
    for (int i = tid; i < 224;   i += blockDim.x) sb2[i]  = gen_b2[i];
    for (int i = tid; i < 3136;  i += blockDim.x) scW1[i] = cf_W1[i];
    for (int i = tid; i < 224;   i += blockDim.x) scb1[i] = cf_b1[i];
    for (int i = tid; i < 224;   i += blockDim.x) scW2[i] = cf_W2[i];
    for (int i = tid; i < 7;     i += blockDim.x) scb2[i] = cf_b2[i];
    for (int i = tid; i < 1568;  i += blockDim.x) {
        int l = i / 224, d = i % 224;
        sgWT[i] = gw[d * 7 + l];
    }
    for (int i = tid; i < 7;     i += blockDim.x) sgb[i]  = gb[i];
    __syncthreads();

    const int wid  = tid >> 5;
    const int lane = tid & 31;
    float* myrow = rows + (wid * 32 + lane) * K1_ROW;

    const int gwarp = blockIdx.x * K1_WARPS + wid;
    const int nwarp = gridDim.x * K1_WARPS;

    for (int blk = gwarp; blk < NBLK; blk += nwarp) {
        const int b = blk * 32 + lane;
        u64 gacc[7];
#pragma unroll
        for (int l = 0; l < 7; l++) gacc[l] = 0ull;

        for (int c = 0; c < NL; c++) {
            // ---- x[14] coalesced from blocked z ----
            float x[14];
            const float* zb = g_z_blk + (size_t)blk * 3136 + c * 14 * 32 + lane;
#pragma unroll
            for (int q = 0; q < 14; q++) x[q] = zb[q * 32];

            // ---- stage 1: h = x @ W1 + b1, two 32-col chunks ----
            float s1 = 0.0f, s2 = 0.0f;
            for (int chunk = 0; chunk < 2; chunk++) {
                u64 h[16];
                {
                    const ulonglong2* bp = (const ulonglong2*)(sb1 + c * 64 + chunk * 32);
#pragma unroll
                    for (int k = 0; k < 8; k++) {
                        ulonglong2 bv = bp[k];
                        h[2 * k] = bv.x; h[2 * k + 1] = bv.y;
                    }
                }
                const float* Wb = sW1 + c * (14 * 64) + chunk * 32;
#pragma unroll
                for (int q = 0; q < 14; q++) {
                    u64 xd = dup2(x[q]);
                    const ulonglong2* wr = (const ulonglong2*)(Wb + q * 64);
#pragma unroll
                    for (int jj = 0; jj < 8; jj++) {
                        ulonglong2 w = wr[jj];
                        h[2 * jj]     = ffma2(xd, w.x, h[2 * jj]);
                        h[2 * jj + 1] = ffma2(xd, w.y, h[2 * jj + 1]);
                    }
                }
                u64 sp = h[0], qp = mul2(h[0], h[0]);
#pragma unroll
                for (int k = 1; k < 16; k++) {
                    sp = add2(sp, h[k]);
                    qp = ffma2(h[k], h[k], qp);
                }
                float2 fs = unpack2(sp), fq = unpack2(qp);
                s1 += fs.x + fs.y;
                s2 += fq.x + fq.y;
                float4* hst = (float4*)(myrow + chunk * 32);
#pragma unroll
                for (int k = 0; k < 8; k++) {
                    float2 lo = unpack2(h[2 * k]);
                    float2 hi = unpack2(h[2 * k + 1]);
                    hst[k] = make_float4(lo.x, lo.y, hi.x, hi.y);
                }
            }
            const float m  = s1 * (1.0f / 64.0f);
            const float var = fmaxf(s2 * (1.0f / 64.0f) - m * m, 0.0f);
            const float iv  = rsqrtf(var + 1e-5f);

            // ---- stage 2: t = ACT(LN(h)) @ W2 + b2 (fused) ----
            u64 t[16];
            {
                const ulonglong2* bp = (const ulonglong2*)(sb2 + c * 32);
#pragma unroll
                for (int k = 0; k < 8; k++) {
                    ulonglong2 bv = bp[k];
                    t[2 * k] = bv.x; t[2 * k + 1] = bv.y;
                }
            }
            for (int r0 = 0; r0 < 16; r0++) {
                float4 hv = ((const float4*)myrow)[r0];
                float4 gv = *(const float4*)(sg + c * 64 + r0 * 4);
                float4 bv = *(const float4*)(sbe + c * 64 + r0 * 4);
#pragma unroll
                for (int r = 0; r < 4; r++) {
                    float hh = (r == 0) ? hv.x : (r == 1) ? hv.y : (r == 2) ? hv.z : hv.w;
                    float gg = (r == 0) ? gv.x : (r == 1) ? gv.y : (r == 2) ? gv.z : gv.w;
                    float bb = (r == 0) ? bv.x : (r == 1) ? bv.y : (r == 2) ? bv.z : bv.w;
                    float av = colony_act(c, fmaf((hh - m) * iv, gg, bb));
                    u64 ad = dup2(av);
                    const ulonglong2* wr = (const ulonglong2*)(sW2 + c * 2048 + (r0 * 4 + r) * 32);
#pragma unroll
                    for (int k = 0; k < 8; k++) {
                        ulonglong2 w = wr[k];
                        t[2 * k]     = ffma2(ad, w.x, t[2 * k]);
                        t[2 * k + 1] = ffma2(ad, w.y, t[2 * k + 1]);
                    }
                }
            }
            // ---- l2norm ----
            u64 nq = mul2(t[0], t[0]);
#pragma unroll
            for (int k = 1; k < 16; k++) nq = ffma2(t[k], t[k], nq);
            float2 nf = unpack2(nq);
            u64 nd = dup2(rsqrtf(fmaxf(nf.x + nf.y, 1e-24f)));
#pragma unroll
            for (int k = 0; k < 16; k++) t[k] = mul2(t[k], nd);

            // ---- store blocked traces (coalesced STG.32 per dim) ----
            {
                float* tb = g_traces_blk + (size_t)blk * 7168 + c * 1024 + lane;
#pragma unroll
                for (int k = 0; k < 16; k++) {
                    float2 f = unpack2(t[k]);
                    tb[(2 * k) * 32]     = f.x;
                    tb[(2 * k + 1) * 32] = f.y;
                }
            }
            // ---- accumulate gates ----
#pragma unroll
            for (int l = 0; l < 7; l++) {
                const ulonglong2* gp = (const ulonglong2*)(sgWT + l * 224 + c * 32);
                u64 acc = gacc[l];
#pragma unroll
                for (int k = 0; k < 8; k++) {
                    ulonglong2 w = gp[k];
                    acc = ffma2(t[2 * k], w.x, acc);
                    acc = ffma2(t[2 * k + 1], w.y, acc);
                }
                gacc[l] = acc;
            }
            // ---- confidence head ----
            {
                u64 hc[16];
                const ulonglong2* bp = (const ulonglong2*)(scb1 + c * 32);
#pragma unroll
                for (int k = 0; k < 8; k++) {
                    ulonglong2 bv = bp[k];
                    hc[2 * k] = bv.x; hc[2 * k + 1] = bv.y;
                }
                const float* cw = scW1 + c * 448;
#pragma unroll
                for (int q = 0; q < 14; q++) {
                    u64 xd = dup2(x[q]);
                    const ulonglong2* wr = (const ulonglong2*)(cw + q * 32);
#pragma unroll
                    for (int k = 0; k < 8; k++) {
                        ulonglong2 w = wr[k];
                        hc[2 * k]     = ffma2(xd, w.x, hc[2 * k]);
                        hc[2 * k + 1] = ffma2(xd, w.y, hc[2 * k + 1]);
                    }
                }
                float dacc = 0.0f;
                const u64* w2p = (const u64*)(scW2 + c * 32);
#pragma unroll
                for (int k = 0; k < 16; k++) {
                    float2 hh = unpack2(hc[k]);
                    float2 ww = unpack2(w2p[k]);
                    dacc = fmaf(fmaxf(hh.x, 0.0f), ww.x, dacc);
                    dacc = fmaf(fmaxf(hh.y, 0.0f), ww.y, dacc);
                }
                myrow[64 + c] = fast_sigmoid(dacc + scb2[c]);
            }
        }

        // ---- gates final + stores ----
        float gate[7];
#pragma unroll
        for (int l = 0; l < 7; l++) {
            float2 f = unpack2(gacc[l]);
            gate[l] = fast_sigmoid(f.x + f.y + sgb[l]);
            g_gates_T[(size_t)l * B_TOTAL + b] = gate[l];
        }
        float cf[7];
#pragma unroll
        for (int i = 0; i < 7; i++) cf[i] = myrow[64 + i];
#pragma unroll
        for (int j = 0; j < 21; j++) {
            float gl = gate[j / 3];
            float v = (gl >= 0.3f) ? cf[FSRC[j]] * cf[FPAR[j]] * gl : 0.0f;
            out_conf[(size_t)b * 21 + j] = v;
        }
    }
}

// ============================================================================
// Kernel 2: lane = 1 batch; 14 warps (rows shrunk to 68); coalesced x;
// outputs staged into row then cooperatively stored coalesced.
// ============================================================================
#define K2_WARPS 14
#define K2_THREADS (K2_WARPS * 32)
#define K2_BLK_PER_LINE 21
#define K2_GRID (NL * K2_BLK_PER_LINE)
#define K2_ROW 68    // h [0,64) | pad 4 ; 68 = 4*17 -> conflict-free float4
#define K2_WSZ (6368 + K2_WARPS * 32 * K2_ROW)
#define K2_SMEM (K2_WSZ * 4)

__global__ void __launch_bounds__(K2_THREADS, 1)
colony_k2(const float* __restrict__ cW1, const float* __restrict__ cb1,
          const float* __restrict__ cg,  const float* __restrict__ cbe,
          const float* __restrict__ cW2, const float* __restrict__ cb2,
          float* __restrict__ out)
{
    extern __shared__ __align__(16) float sm[];
    float* sW1 = sm;            // [64][64]
    float* sW2 = sW1 + 4096;    // [64][32]
    float* sb1 = sW2 + 2048;
    float* sgl = sb1 + 64;
    float* sbe = sgl + 64;
    float* sb2 = sbe + 64;
    float* stile = sb2 + 32;

    const int line = blockIdx.x % NL;
    const int tid = threadIdx.x;
    {
        const float* w1 = cW1 + line * 4096;
        const float* w2 = cW2 + line * 2048;
        for (int i = tid; i < 4096; i += blockDim.x) sW1[i] = w1[i];
        for (int i = tid; i < 2048; i += blockDim.x) sW2[i] = w2[i];
        if (tid < 64) {
            sb1[tid] = cb1[line * 64 + tid];
            sgl[tid] = cg[line * 64 + tid];
            sbe[tid] = cbe[line * 64 + tid];
        }
        if (tid < 32) sb2[tid] = cb2[line * 32 + tid];
    }
    __syncthreads();

    const int wid  = tid >> 5;
    const int lane = tid & 31;
    float* myrow = stile + (wid * 32 + lane) * K2_ROW;
    float* wrows = stile + (wid * 32) * K2_ROW;

    const int col0 = FSRC[line * 3 + 0];
    const int col1 = FSRC[line * 3 + 1];
    const int col2 = FSRC[line * 3 + 2];

    const int lwarp = (blockIdx.x / NL) * K2_WARPS + wid;
    const int nlw   = K2_BLK_PER_LINE * K2_WARPS;   // 294
    const int ngroups = NBLK;                        // 2048

    for (int g = lwarp; g < ngroups; g += nlw) {
        const int b = g * 32 + lane;

        const float gate = g_gates_T[(size_t)line * B_TOTAL + b];
        const float scl = (gate >= 0.3f) ? gate : 0.0f;

        for (int p = 0; p < 3; p++) {
            const int cS = (p == 0) ? col0 : (p == 1) ? col1 : col2;
            const int cP = (p == 0) ? col1 : (p == 1) ? col2 : col0;

            // ---- stage 1: h in two 32-col chunks; x coalesced ----
            float s1 = 0.0f, s2 = 0.0f;
            for (int chunk = 0; chunk < 2; chunk++) {
                u64 h[16];
                {
                    const ulonglong2* bp = (const ulonglong2*)(sb1 + chunk * 32);
#pragma unroll
                    for (int k = 0; k < 8; k++) {
                        ulonglong2 bv = bp[k];
                        h[2 * k] = bv.x; h[2 * k + 1] = bv.y;
                    }
                }
                for (int half = 0; half < 2; half++) {
                    const int colony = half ? cP : cS;
                    const float* x = g_traces_blk + (size_t)g * 7168 + colony * 1024 + lane;
                    const float* Wb = sW1 + half * 2048 + chunk * 32;
#pragma unroll 8
                    for (int i = 0; i < 32; i++) {
                        u64 xd = dup2(x[i * 32]);     // coalesced LDG.32
                        const ulonglong2* wr = (const ulonglong2*)(Wb + i * 64);
#pragma unroll
                        for (int jj = 0; jj < 8; jj++) {
                            ulonglong2 w = wr[jj];
                            h[2 * jj]     = ffma2(xd, w.x, h[2 * jj]);
                            h[2 * jj + 1] = ffma2(xd, w.y, h[2 * jj + 1]);
                        }
                    }
                }
                u64 sp = h[0], qp = mul2(h[0], h[0]);
#pragma unroll
                for (int k = 1; k < 16; k++) {
                    sp = add2(sp, h[k]);
                    qp = ffma2(h[k], h[k], qp);
                }
                float2 fs = unpack2(sp), fq = unpack2(qp);
                s1 += fs.x + fs.y;
                s2 += fq.x + fq.y;
                float4* hst = (float4*)(myrow + chunk * 32);
#pragma unroll
                for (int k = 0; k < 8; k++) {
                    float2 lo = unpack2(h[2 * k]);
                    float2 hi = unpack2(h[2 * k + 1]);
                    hst[k] = make_float4(lo.x, lo.y, hi.x, hi.y);
                }
            }
            const float m  = s1 * (1.0f / 64.0f);
            const float var = fmaxf(s2 * (1.0f / 64.0f) - m * m, 0.0f);
            const float iv  = rsqrtf(var + 1e-5f);

            // ---- stage 2: fused LN-apply + ReLU, t = a @ W2 + b2 ----
            u64 t[16];
            {
                const ulonglong2* bp = (const ulonglong2*)sb2;
#pragma unroll
                for (int k = 0; k < 8; k++) {
                    ulonglong2 bv = bp[k];
                    t[2 * k] = bv.x; t[2 * k + 1] = bv.y;
                }
            }
#pragma unroll 4
            for (int r0 = 0; r0 < 16; r0++) {
                float4 hv = ((const float4*)myrow)[r0];
                float4 gv = ((const float4*)sgl)[r0];
                float4 bv = ((const float4*)sbe)[r0];
#pragma unroll
                for (int r = 0; r < 4; r++) {
                    float hh = (r == 0) ? hv.x : (r == 1) ? hv.y : (r == 2) ? hv.z : hv.w;
                    float gg = (r == 0) ? gv.x : (r == 1) ? gv.y : (r == 2) ? gv.z : gv.w;
                    float bb = (r == 0) ? bv.x : (r == 1) ? bv.y : (r == 2) ? bv.z : bv.w;
                    float av = fmaxf(fmaf((hh - m) * iv, gg, bb), 0.0f);
                    u64 ad = dup2(av);
                    const ulonglong2* wr = (const ulonglong2*)(sW2 + (r0 * 4 + r) * 32);
#pragma unroll
                    for (int k = 0; k < 8; k++) {
                        ulonglong2 w = wr[k];
                        t[2 * k]     = ffma2(ad, w.x, t[2 * k]);
                        t[2 * k + 1] = ffma2(ad, w.y, t[2 * k + 1]);
                    }
                }
            }

            // ---- l2norm + gate; park output in row (h dead) ----
            {
                u64 nq = mul2(t[0], t[0]);
#pragma unroll
                for (int k = 1; k < 16; k++) nq = ffma2(t[k], t[k], nq);
                float2 nf = unpack2(nq);
                u64 sc2 = dup2(scl * rsqrtf(fmaxf(nf.x + nf.y, 1e-24f)));
                float4* o = (float4*)myrow;
#pragma unroll
                for (int k = 0; k < 8; k++) {
                    float2 o0 = unpack2(mul2(t[2 * k], sc2));
                    float2 o1 = unpack2(mul2(t[2 * k + 1], sc2));
                    o[k] = make_float4(o0.x, o0.y, o1.x, o1.y);
                }
            }
            __syncwarp();

            // ---- cooperative coalesced store: 32 batch rows ----
            for (int k = lane; k < 256; k += 32) {
                int mm = k >> 3, j = k & 7;
                float4 v = *(const float4*)(wrows + mm * K2_ROW + j * 4);
                size_t row = (((size_t)(g * 32 + mm) * 7 + line) * 3 + p) * 32;
                *(float4*)(out + row + j * 4) = v;
            }
            __syncwarp();
        }
    }
}

// ============================================================================
extern "C" void kernel_launch(void* const* d_in, const int* in_sizes, int n_in,
                              void* d_out, int out_size)
{
    const float* z      = (const float*)d_in[0];
    const float* gen_W1 = (const float*)d_in[1];
    const float* gen_b1 = (const float*)d_in[2];
    const float* gen_g  = (const float*)d_in[3];
    const float* gen_be = (const float*)d_in[4];
    const float* gen_W2 = (const float*)d_in[5];
    const float* gen_b2 = (const float*)d_in[6];
    const float* cf_W1  = (const float*)d_in[7];
    const float* cf_b1  = (const float*)d_in[8];
    const float* cf_W2  = (const float*)d_in[9];
    const float* cf_b2  = (const float*)d_in[10];
    const float* g_W    = (const float*)d_in[11];
    const float* g_b    = (const float*)d_in[12];
    const float* c_W1   = (const float*)d_in[13];
    const float* c_b1   = (const float*)d_in[14];
    const float* c_g    = (const float*)d_in[15];
    const float* c_be   = (const float*)d_in[16];
    const float* c_W2   = (const float*)d_in[17];
    const float* c_b2   = (const float*)d_in[18];

    float* out      = (float*)d_out;                       // composed [B,7,3,32]
    float* out_conf = out + (size_t)B_TOTAL * 672;         // comp_conf [B,7,3]

    cudaFuncSetAttribute(colony_k1, cudaFuncAttributeMaxDynamicSharedMemorySize, K1_SMEM);
    cudaFuncSetAttribute(colony_k2, cudaFuncAttributeMaxDynamicSharedMemorySize, K2_SMEM);

    colony_kz<<<NBLK, 256>>>(z);
    colony_k1<<<148, K1_THREADS, K1_SMEM>>>(gen_W1, gen_b1, gen_g, gen_be, gen_W2, gen_b2,
                                            cf_W1, cf_b1, cf_W2, cf_b2, g_W, g_b, out_conf);
    colony_k2<<<K2_GRID, K2_THREADS, K2_SMEM>>>(c_W1, c_b1, c_g, c_be, c_W2, c_b2, out);
}

// round 14
// speedup vs baseline: 1.1526x; 1.1526x over previous
#include <cuda_runtime.h>
#include <math.h>

#define B_TOTAL 65536
#define NBLK (B_TOTAL / 32)
#define NL 7

typedef unsigned long long u64;

// ---- scratch (static device globals) ----
__device__ __align__(16) float g_traces_blk[(size_t)B_TOTAL * 224];   // [blk][c][d][32]
__device__ __align__(16) float g_gates_T[(size_t)NL * B_TOTAL];       // [line][b]
__device__ __align__(16) float g_z_blk[(size_t)B_TOTAL * 98];         // [blk][98][32]

__constant__ int FSRC[21] = {0,1,2, 0,3,4, 0,5,6, 1,3,5, 1,4,6, 2,3,6, 2,4,5};
__constant__ int FPAR[21] = {1,2,0, 3,4,0, 5,6,0, 3,5,1, 4,6,1, 3,6,2, 4,5,2};

__device__ __forceinline__ u64 pack2(float x, float y) {
    u64 r; asm("mov.b64 %0, {%1,%2};" : "=l"(r) : "f"(x), "f"(y)); return r;
}
__device__ __forceinline__ float2 unpack2(u64 v) {
    float2 r; asm("mov.b64 {%0,%1}, %2;" : "=f"(r.x), "=f"(r.y) : "l"(v)); return r;
}
__device__ __forceinline__ u64 dup2(float x) { return pack2(x, x); }
__device__ __forceinline__ u64 ffma2(u64 a, u64 b, u64 c) {
    u64 d; asm("fma.rn.f32x2 %0, %1, %2, %3;" : "=l"(d) : "l"(a), "l"(b), "l"(c)); return d;
}
__device__ __forceinline__ u64 add2(u64 a, u64 b) {
    u64 d; asm("add.rn.f32x2 %0, %1, %2;" : "=l"(d) : "l"(a), "l"(b)); return d;
}
__device__ __forceinline__ u64 mul2(u64 a, u64 b) {
    u64 d; asm("mul.rn.f32x2 %0, %1, %2;" : "=l"(d) : "l"(a), "l"(b)); return d;
}

__device__ __forceinline__ float fast_sigmoid(float x) {
    return __fdividef(1.0f, 1.0f + __expf(-x));
}

__device__ __forceinline__ float colony_act(int c, float x) {
    switch (c) {
        case 0: return fmaxf(x, 0.0f);
        case 1: { float e = __expf(2.0f * x); return 1.0f - __fdividef(2.0f, e + 1.0f); }
        case 2: return 0.5f * x * (1.0f + erff(x * 0.7071067811865476f));
        case 3: return x * fast_sigmoid(x);
        case 4: return fmaxf(x, 0.0f) + log1pf(__expf(-fabsf(x)));
        case 5: return fast_sigmoid(x);
        default: return fminf(fmaxf(x, -1.0f), 1.0f);
    }
}

// ============================================================================
// Kernel Z: transpose z [B][98] -> z_blk [blk][98][32]  (pure bandwidth)
// ============================================================================
__global__ void __launch_bounds__(256, 4)
colony_kz(const float* __restrict__ z)
{
    __shared__ float tile[32 * 99];
    const int blk = blockIdx.x;
    const float* src = z + (size_t)blk * 3136;
    for (int idx = threadIdx.x; idx < 3136; idx += 256) {
        int b = idx / 98, q = idx % 98;
        tile[b * 99 + q] = src[idx];
    }
    __syncthreads();
    float* dst = g_z_blk + (size_t)blk * 3136;
    for (int idx = threadIdx.x; idx < 3136; idx += 256) {
        int q = idx >> 5, bb = idx & 31;
        dst[idx] = tile[bb * 99 + q];
    }
}

// ============================================================================
// Kernel 1: lane = batch; 12 warps, row 76 (proven inner code from R12).
// ============================================================================
#define K1_WARPS 12
#define K1_THREADS (K1_WARPS * 32)
#define K1_ROW 76    // h [0,64) | conf [64,71) | pad ; 76/4=19 odd -> conflict-free float4
#define K1_WSZ (27344 + K1_WARPS * 32 * K1_ROW)
#define K1_SMEM (K1_WSZ * 4)

__global__ void __launch_bounds__(K1_THREADS, 1)
colony_k1(const float* __restrict__ gen_W1, const float* __restrict__ gen_b1,
          const float* __restrict__ gen_g,  const float* __restrict__ gen_be,
          const float* __restrict__ gen_W2, const float* __restrict__ gen_b2,
          const float* __restrict__ cf_W1,  const float* __restrict__ cf_b1,
          const float* __restrict__ cf_W2,  const float* __restrict__ cf_b2,
          const float* __restrict__ gw,     const float* __restrict__ gb,
          float* __restrict__ out_conf)
{
    extern __shared__ __align__(16) float sm[];
    float* sW1  = sm;            // 6272  [7][14][64]
    float* sb1  = sW1  + 6272;   // 448
    float* sg   = sb1  + 448;    // 448
    float* sbe  = sg   + 448;    // 448
    float* sW2  = sbe  + 448;    // 14336 [7][64][32]
    float* sb2  = sW2  + 14336;  // 224
    float* scW1 = sb2  + 224;    // 3136  [7][14][32]
    float* scb1 = scW1 + 3136;   // 224
    float* scW2 = scb1 + 224;    // 224
    float* scb2 = scW2 + 224;    // 8
    float* sgWT = scb2 + 8;      // 1568  transposed [7][224]
    float* sgb  = sgWT + 1568;   // 8
    float* rows = sgb  + 8;

    const int tid = threadIdx.x;
    for (int i = tid; i < 6272;  i += blockDim.x) sW1[i]  = gen_W1[i];
    for (int i = tid; i < 448;   i += blockDim.x) sb1[i]  = gen_b1[i];
    for (int i = tid; i < 448;   i += blockDim.x) sg[i]   = gen_g[i];
    for (int i = tid; i < 448;   i += blockDim.x) sbe[i]  = gen_be[i];
    for (int i = tid; i < 14336; i += blockDim.x) sW2[i]  = gen_W2[i];
    for (int i = tid; i < 224;   i += blockDim.x) sb2[i]  = gen_b2[i];
    for (int i = tid; i < 3136;  i += blockDim.x) scW1[i] = cf_W1[i];
    for (int i = tid; i < 224;   i += blockDim.x) scb1[i] = cf_b1[i];
    for (int i = tid; i < 224;   i += blockDim.x) scW2[i] = cf_W2[i];
    for (int i = tid; i < 7;     i += blockDim.x) scb2[i] = cf_b2[i];
    for (int i = tid; i < 1568;  i += blockDim.x) {
        int l = i / 224, d = i % 224;
        sgWT[i] = gw[d * 7 + l];
    }
    for (int i = tid; i < 7;     i += blockDim.x) sgb[i]  = gb[i];
    __syncthreads();

    const int wid  = tid >> 5;
    const int lane = tid & 31;
    float* myrow = rows + (wid * 32 + lane) * K1_ROW;

    const int gwarp = blockIdx.x * K1_WARPS + wid;
    const int nwarp = gridDim.x * K1_WARPS;

    for (int blk = gwarp; blk < NBLK; blk += nwarp) {
        const int b = blk * 32 + lane;
        u64 gacc[7];
#pragma unroll
        for (int l = 0; l < 7; l++) gacc[l] = 0ull;

        for (int c = 0; c < NL; c++) {
            float x[14];
            const float* zb = g_z_blk + (size_t)blk * 3136 + c * 14 * 32 + lane;
#pragma unroll
            for (int q = 0; q < 14; q++) x[q] = zb[q * 32];

            // ---- stage 1: h = x @ W1 + b1, two 32-col chunks ----
            float s1 = 0.0f, s2 = 0.0f;
            for (int chunk = 0; chunk < 2; chunk++) {
                u64 h[16];
                {
                    const ulonglong2* bp = (const ulonglong2*)(sb1 + c * 64 + chunk * 32);
#pragma unroll
                    for (int k = 0; k < 8; k++) {
                        ulonglong2 bv = bp[k];
                        h[2 * k] = bv.x; h[2 * k + 1] = bv.y;
                    }
                }
                const float* Wb = sW1 + c * (14 * 64) + chunk * 32;
#pragma unroll
                for (int q = 0; q < 14; q++) {
                    u64 xd = dup2(x[q]);
                    const ulonglong2* wr = (const ulonglong2*)(Wb + q * 64);
#pragma unroll
                    for (int jj = 0; jj < 8; jj++) {
                        ulonglong2 w = wr[jj];
                        h[2 * jj]     = ffma2(xd, w.x, h[2 * jj]);
                        h[2 * jj + 1] = ffma2(xd, w.y, h[2 * jj + 1]);
                    }
                }
                u64 sp = h[0], qp = mul2(h[0], h[0]);
#pragma unroll
                for (int k = 1; k < 16; k++) {
                    sp = add2(sp, h[k]);
                    qp = ffma2(h[k], h[k], qp);
                }
                float2 fs = unpack2(sp), fq = unpack2(qp);
                s1 += fs.x + fs.y;
                s2 += fq.x + fq.y;
                float4* hst = (float4*)(myrow + chunk * 32);
#pragma unroll
                for (int k = 0; k < 8; k++) {
                    float2 lo = unpack2(h[2 * k]);
                    float2 hi = unpack2(h[2 * k + 1]);
                    hst[k] = make_float4(lo.x, lo.y, hi.x, hi.y);
                }
            }
            const float m  = s1 * (1.0f / 64.0f);
            const float var = fmaxf(s2 * (1.0f / 64.0f) - m * m, 0.0f);
            const float iv  = rsqrtf(var + 1e-5f);

            // ---- stage 2: t = ACT(LN(h)) @ W2 + b2 (fused) ----
            u64 t[16];
            {
                const ulonglong2* bp = (const ulonglong2*)(sb2 + c * 32);
#pragma unroll
                for (int k = 0; k < 8; k++) {
                    ulonglong2 bv = bp[k];
                    t[2 * k] = bv.x; t[2 * k + 1] = bv.y;
                }
            }
            for (int r0 = 0; r0 < 16; r0++) {
                float4 hv = ((const float4*)myrow)[r0];
                float4 gv = *(const float4*)(sg + c * 64 + r0 * 4);
                float4 bv = *(const float4*)(sbe + c * 64 + r0 * 4);
#pragma unroll
                for (int r = 0; r < 4; r++) {
                    float hh = (r == 0) ? hv.x : (r == 1) ? hv.y : (r == 2) ? hv.z : hv.w;
                    float gg = (r == 0) ? gv.x : (r == 1) ? gv.y : (r == 2) ? gv.z : gv.w;
                    float bb = (r == 0) ? bv.x : (r == 1) ? bv.y : (r == 2) ? bv.z : bv.w;
                    float av = colony_act(c, fmaf((hh - m) * iv, gg, bb));
                    u64 ad = dup2(av);
                    const ulonglong2* wr = (const ulonglong2*)(sW2 + c * 2048 + (r0 * 4 + r) * 32);
#pragma unroll
                    for (int k = 0; k < 8; k++) {
                        ulonglong2 w = wr[k];
                        t[2 * k]     = ffma2(ad, w.x, t[2 * k]);
                        t[2 * k + 1] = ffma2(ad, w.y, t[2 * k + 1]);
                    }
                }
            }
            // ---- l2norm ----
            u64 nq = mul2(t[0], t[0]);
#pragma unroll
            for (int k = 1; k < 16; k++) nq = ffma2(t[k], t[k], nq);
            float2 nf = unpack2(nq);
            u64 nd = dup2(rsqrtf(fmaxf(nf.x + nf.y, 1e-24f)));
#pragma unroll
            for (int k = 0; k < 16; k++) t[k] = mul2(t[k], nd);

            // ---- store blocked traces ----
            {
                float* tb = g_traces_blk + (size_t)blk * 7168 + c * 1024 + lane;
#pragma unroll
                for (int k = 0; k < 16; k++) {
                    float2 f = unpack2(t[k]);
                    tb[(2 * k) * 32]     = f.x;
                    tb[(2 * k + 1) * 32] = f.y;
                }
            }
            // ---- accumulate gates ----
#pragma unroll
            for (int l = 0; l < 7; l++) {
                const ulonglong2* gp = (const ulonglong2*)(sgWT + l * 224 + c * 32);
                u64 acc = gacc[l];
#pragma unroll
                for (int k = 0; k < 8; k++) {
                    ulonglong2 w = gp[k];
                    acc = ffma2(t[2 * k], w.x, acc);
                    acc = ffma2(t[2 * k + 1], w.y, acc);
                }
                gacc[l] = acc;
            }
            // ---- confidence head ----
            {
                u64 hc[16];
                const ulonglong2* bp = (const ulonglong2*)(scb1 + c * 32);
#pragma unroll
                for (int k = 0; k < 8; k++) {
                    ulonglong2 bv = bp[k];
                    hc[2 * k] = bv.x; hc[2 * k + 1] = bv.y;
                }
                const float* cw = scW1 + c * 448;
#pragma unroll
                for (int q = 0; q < 14; q++) {
                    u64 xd = dup2(x[q]);
                    const ulonglong2* wr = (const ulonglong2*)(cw + q * 32);
#pragma unroll
                    for (int k = 0; k < 8; k++) {
                        ulonglong2 w = wr[k];
                        hc[2 * k]     = ffma2(xd, w.x, hc[2 * k]);
                        hc[2 * k + 1] = ffma2(xd, w.y, hc[2 * k + 1]);
                    }
                }
                float dacc = 0.0f;
                const u64* w2p = (const u64*)(scW2 + c * 32);
#pragma unroll
                for (int k = 0; k < 16; k++) {
                    float2 hh = unpack2(hc[k]);
                    float2 ww = unpack2(w2p[k]);
                    dacc = fmaf(fmaxf(hh.x, 0.0f), ww.x, dacc);
                    dacc = fmaf(fmaxf(hh.y, 0.0f), ww.y, dacc);
                }
                myrow[64 + c] = fast_sigmoid(dacc + scb2[c]);
            }
        }

        // ---- gates final + stores ----
        float gate[7];
#pragma unroll
        for (int l = 0; l < 7; l++) {
            float2 f = unpack2(gacc[l]);
            gate[l] = fast_sigmoid(f.x + f.y + sgb[l]);
            g_gates_T[(size_t)l * B_TOTAL + b] = gate[l];
        }
        float cf[7];
#pragma unroll
        for (int i = 0; i < 7; i++) cf[i] = myrow[64 + i];
#pragma unroll
        for (int j = 0; j < 21; j++) {
            float gl = gate[j / 3];
            float v = (gl >= 0.3f) ? cf[FSRC[j]] * cf[FPAR[j]] * gl : 0.0f;
            out_conf[(size_t)b * 21 + j] = v;
        }
    }
}

// ============================================================================
// Kernel 2: lane = 2 batches (R12 proven core), bumped to 11 warps.
// ============================================================================
#define K2_WARPS 11
#define K2_THREADS (K2_WARPS * 32)
#define K2_BLK_PER_LINE 21
#define K2_GRID (NL * K2_BLK_PER_LINE)
#define K2_ROW 132
#define K2_WSZ (6368 + K2_WARPS * 32 * K2_ROW)
#define K2_SMEM (K2_WSZ * 4)

__global__ void __launch_bounds__(K2_THREADS, 1)
colony_k2(const float* __restrict__ cW1, const float* __restrict__ cb1,
          const float* __restrict__ cg,  const float* __restrict__ cbe,
          const float* __restrict__ cW2, const float* __restrict__ cb2,
          float* __restrict__ out)
{
    extern __shared__ __align__(16) float sm[];
    float* sW1 = sm;
    float* sW2 = sW1 + 4096;
    float* sb1 = sW2 + 2048;
    float* sgl = sb1 + 64;
    float* sbe = sgl + 64;
    float* sb2 = sbe + 64;
    float* stile = sb2 + 32;

    const int line = blockIdx.x % NL;
    const int tid = threadIdx.x;
    {
        const float* w1 = cW1 + line * 4096;
        const float* w2 = cW2 + line * 2048;
        for (int i = tid; i < 4096; i += blockDim.x) sW1[i] = w1[i];
        for (int i = tid; i < 2048; i += blockDim.x) sW2[i] = w2[i];
        if (tid < 64) {
            sb1[tid] = cb1[line * 64 + tid];
            sgl[tid] = cg[line * 64 + tid];
            sbe[tid] = cbe[line * 64 + tid];
        }
        if (tid < 32) sb2[tid] = cb2[line * 32 + tid];
    }
    __syncthreads();

    const int wid  = tid >> 5;
    const int lane = tid & 31;
    float* myrow = stile + (wid * 32 + lane) * K2_ROW;
    float* wrows = stile + (wid * 32) * K2_ROW;

    const int col0 = FSRC[line * 3 + 0];
    const int col1 = FSRC[line * 3 + 1];
    const int col2 = FSRC[line * 3 + 2];

    const int lwarp = (blockIdx.x / NL) * K2_WARPS + wid;
    const int nlw   = K2_BLK_PER_LINE * K2_WARPS;   // 231
    const int ngroups = B_TOTAL / 64;               // 1024

    for (int g = lwarp; g < ngroups; g += nlw) {
        const int blkA = 2 * g, blkB = 2 * g + 1;
        const int bA = g * 64 + lane;
        const int bB = bA + 32;

        const float gateA = g_gates_T[(size_t)line * B_TOTAL + bA];
        const float gateB = g_gates_T[(size_t)line * B_TOTAL + bB];
        const float sclA = (gateA >= 0.3f) ? gateA : 0.0f;
        const float sclB = (gateB >= 0.3f) ? gateB : 0.0f;

        for (int p = 0; p < 3; p++) {
            const int cS = (p == 0) ? col0 : (p == 1) ? col1 : col2;
            const int cP = (p == 0) ? col1 : (p == 1) ? col2 : col0;

            float s1A = 0.0f, s2A = 0.0f, s1B = 0.0f, s2B = 0.0f;
            for (int chunk = 0; chunk < 2; chunk++) {
                u64 hA[16], hB[16];
                {
                    const ulonglong2* bp = (const ulonglong2*)(sb1 + chunk * 32);
#pragma unroll
                    for (int k = 0; k < 8; k++) {
                        ulonglong2 bv = bp[k];
                        hA[2 * k] = bv.x; hA[2 * k + 1] = bv.y;
                        hB[2 * k] = bv.x; hB[2 * k + 1] = bv.y;
                    }
                }
                for (int half = 0; half < 2; half++) {
                    const int colony = half ? cP : cS;
                    const float* xA = g_traces_blk + (size_t)blkA * 7168 + colony * 1024 + lane;
                    const float* xB = g_traces_blk + (size_t)blkB * 7168 + colony * 1024 + lane;
                    const float* Wb = sW1 + half * 2048 + chunk * 32;
#pragma unroll 8
                    for (int i = 0; i < 32; i++) {
                        u64 aD = dup2(xA[i * 32]);
                        u64 bD = dup2(xB[i * 32]);
                        const ulonglong2* wr = (const ulonglong2*)(Wb + i * 64);
#pragma unroll
                        for (int jj = 0; jj < 8; jj++) {
                            ulonglong2 w = wr[jj];
                            hA[2 * jj]     = ffma2(aD, w.x, hA[2 * jj]);
                            hA[2 * jj + 1] = ffma2(aD, w.y, hA[2 * jj + 1]);
                            hB[2 * jj]     = ffma2(bD, w.x, hB[2 * jj]);
                            hB[2 * jj + 1] = ffma2(bD, w.y, hB[2 * jj + 1]);
                        }
                    }
                }
                {
                    u64 sAp = hA[0], qAp = mul2(hA[0], hA[0]);
                    u64 sBp = hB[0], qBp = mul2(hB[0], hB[0]);
#pragma unroll
                    for (int k = 1; k < 16; k++) {
                        sAp = add2(sAp, hA[k]); qAp = ffma2(hA[k], hA[k], qAp);
                        sBp = add2(sBp, hB[k]); qBp = ffma2(hB[k], hB[k], qBp);
                    }
                    float2 a1 = unpack2(sAp), a2 = unpack2(qAp);
                    float2 b1 = unpack2(sBp), b2 = unpack2(qBp);
                    s1A += a1.x + a1.y;  s2A += a2.x + a2.y;
                    s1B += b1.x + b1.y;  s2B += b2.x + b2.y;
                }
                {
                    float4* hstA = (float4*)(myrow + chunk * 32);
                    float4* hstB = (float4*)(myrow + 64 + chunk * 32);
#pragma unroll
                    for (int k = 0; k < 8; k++) {
                        float2 lo = unpack2(hA[2 * k]);
                        float2 hi = unpack2(hA[2 * k + 1]);
                        hstA[k] = make_float4(lo.x, lo.y, hi.x, hi.y);
                        lo = unpack2(hB[2 * k]);
                        hi = unpack2(hB[2 * k + 1]);
                        hstB[k] = make_float4(lo.x, lo.y, hi.x, hi.y);
                    }
                }
            }
            const float mA = s1A * (1.0f / 64.0f);
            const float mB = s1B * (1.0f / 64.0f);
            const float ivA = rsqrtf(fmaxf(s2A * (1.0f / 64.0f) - mA * mA, 0.0f) + 1e-5f);
            const float ivB = rsqrtf(fmaxf(s2B * (1.0f / 64.0f) - mB * mB, 0.0f) + 1e-5f);

            u64 tA[16], tB[16];
            {
                const ulonglong2* bp = (const ulonglong2*)sb2;
#pragma unroll
                for (int k = 0; k < 8; k++) {
                    ulonglong2 bv = bp[k];
                    tA[2 * k] = bv.x; tA[2 * k + 1] = bv.y;
                    tB[2 * k] = bv.x; tB[2 * k + 1] = bv.y;
                }
            }
#pragma unroll 4
            for (int r0 = 0; r0 < 16; r0++) {
                float4 hvA = ((const float4*)myrow)[r0];
                float4 hvB = ((const float4*)(myrow + 64))[r0];
                float4 gv = ((const float4*)sgl)[r0];
                float4 bv = ((const float4*)sbe)[r0];
#pragma unroll
                for (int r = 0; r < 4; r++) {
                    float hA1 = (r == 0) ? hvA.x : (r == 1) ? hvA.y : (r == 2) ? hvA.z : hvA.w;
                    float hB1 = (r == 0) ? hvB.x : (r == 1) ? hvB.y : (r == 2) ? hvB.z : hvB.w;
                    float gw1 = (r == 0) ? gv.x : (r == 1) ? gv.y : (r == 2) ? gv.z : gv.w;
                    float bw1 = (r == 0) ? bv.x : (r == 1) ? bv.y : (r == 2) ? bv.z : bv.w;
                    float aAv = fmaxf(fmaf((hA1 - mA) * ivA, gw1, bw1), 0.0f);
                    float aBv = fmaxf(fmaf((hB1 - mB) * ivB, gw1, bw1), 0.0f);
                    u64 aD = dup2(aAv);
                    u64 bD = dup2(aBv);
                    const ulonglong2* wr = (const ulonglong2*)(sW2 + (r0 * 4 + r) * 32);
#pragma unroll
                    for (int k = 0; k < 8; k++) {
                        ulonglong2 w = wr[k];
                        tA[2 * k]     = ffma2(aD, w.x, tA[2 * k]);
                        tA[2 * k + 1] = ffma2(aD, w.y, tA[2 * k + 1]);
                        tB[2 * k]     = ffma2(bD, w.x, tB[2 * k]);
                        tB[2 * k + 1] = ffma2(bD, w.y, tB[2 * k + 1]);
                    }
                }
            }
            {
                u64 nqA = mul2(tA[0], tA[0]);
                u64 nqB = mul2(tB[0], tB[0]);
#pragma unroll
                for (int k = 1; k < 16; k++) {
                    nqA = ffma2(tA[k], tA[k], nqA);
                    nqB = ffma2(tB[k], tB[k], nqB);
                }
                float2 fa = unpack2(nqA), fb = unpack2(nqB);
                u64 scA2 = dup2(sclA * rsqrtf(fmaxf(fa.x + fa.y, 1e-24f)));
                u64 scB2 = dup2(sclB * rsqrtf(fmaxf(fb.x + fb.y, 1e-24f)));
                float4* oA = (float4*)myrow;
                float4* oB = (float4*)(myrow + 64);
#pragma unroll
                for (int k = 0; k < 8; k++) {
                    float2 o0 = unpack2(mul2(tA[2 * k], scA2));
                    float2 o1 = unpack2(mul2(tA[2 * k + 1], scA2));
                    oA[k] = make_float4(o0.x, o0.y, o1.x, o1.y);
                    o0 = unpack2(mul2(tB[2 * k], scB2));
                    o1 = unpack2(mul2(tB[2 * k + 1], scB2));
                    oB[k] = make_float4(o0.x, o0.y, o1.x, o1.y);
                }
            }
            __syncwarp();

            for (int k = lane; k < 256; k += 32) {
                int m = k >> 3, j = k & 7;
                const float* src = wrows + m * K2_ROW;
                float4 vA = *(const float4*)(src + j * 4);
                float4 vB = *(const float4*)(src + 64 + j * 4);
                size_t rowA = (((size_t)(g * 64 + m) * 7 + line) * 3 + p) * 32;
                size_t rowB = (((size_t)(g * 64 + 32 + m) * 7 + line) * 3 + p) * 32;
                *(float4*)(out + rowA + j * 4) = vA;
                *(float4*)(out + rowB + j * 4) = vB;
            }
            __syncwarp();
        }
    }
}

// ============================================================================
extern "C" void kernel_launch(void* const* d_in, const int* in_sizes, int n_in,
                              void* d_out, int out_size)
{
    const float* z      = (const float*)d_in[0];
    const float* gen_W1 = (const float*)d_in[1];
    const float* gen_b1 = (const float*)d_in[2];
    const float* gen_g  = (const float*)d_in[3];
    const float* gen_be = (const float*)d_in[4];
    const float* gen_W2 = (const float*)d_in[5];
    const float* gen_b2 = (const float*)d_in[6];
    const float* cf_W1  = (const float*)d_in[7];
    const float* cf_b1  = (const float*)d_in[8];
    const float* cf_W2  = (const float*)d_in[9];
    const float* cf_b2  = (const float*)d_in[10];
    const float* g_W    = (const float*)d_in[11];
    const float* g_b    = (const float*)d_in[12];
    const float* c_W1   = (const float*)d_in[13];
    const float* c_b1   = (const float*)d_in[14];
    const float* c_g    = (const float*)d_in[15];
    const float* c_be   = (const float*)d_in[16];
    const float* c_W2   = (const float*)d_in[17];
    const float* c_b2   = (const float*)d_in[18];

    float* out      = (float*)d_out;                       // composed [B,7,3,32]
    float* out_conf = out + (size_t)B_TOTAL * 672;         // comp_conf [B,7,3]

    cudaFuncSetAttribute(colony_k1, cudaFuncAttributeMaxDynamicSharedMemorySize, K1_SMEM);
    cudaFuncSetAttribute(colony_k2, cudaFuncAttributeMaxDynamicSharedMemorySize, K2_SMEM);

    colony_kz<<<NBLK, 256>>>(z);
    colony_k1<<<148, K1_THREADS, K1_SMEM>>>(gen_W1, gen_b1, gen_g, gen_be, gen_W2, gen_b2,
                                            cf_W1, cf_b1, cf_W2, cf_b2, g_W, g_b, out_conf);
    colony_k2<<<K2_GRID, K2_THREADS, K2_SMEM>>>(c_W1, c_b1, c_g, c_be, c_W2, c_b2, out);
}

// round 15
// speedup vs baseline: 1.2299x; 1.0671x over previous
#include <cuda_runtime.h>
#include <math.h>

#define B_TOTAL 65536
#define NBLK (B_TOTAL / 32)
#define NL 7

typedef unsigned long long u64;

// ---- scratch (static device globals) ----
__device__ __align__(16) float g_traces_blk[(size_t)B_TOTAL * 224];   // [blk][c][d][32]
__device__ __align__(16) float g_gates_T[(size_t)NL * B_TOTAL];       // [line][b]
__device__ __align__(16) float g_z_blk[(size_t)B_TOTAL * 98];         // [blk][98][32]

__constant__ int FSRC[21] = {0,1,2, 0,3,4, 0,5,6, 1,3,5, 1,4,6, 2,3,6, 2,4,5};
__constant__ int FPAR[21] = {1,2,0, 3,4,0, 5,6,0, 3,5,1, 4,6,1, 3,6,2, 4,5,2};

__device__ __forceinline__ u64 pack2(float x, float y) {
    u64 r; asm("mov.b64 %0, {%1,%2};" : "=l"(r) : "f"(x), "f"(y)); return r;
}
__device__ __forceinline__ float2 unpack2(u64 v) {
    float2 r; asm("mov.b64 {%0,%1}, %2;" : "=f"(r.x), "=f"(r.y) : "l"(v)); return r;
}
__device__ __forceinline__ u64 dup2(float x) { return pack2(x, x); }
__device__ __forceinline__ u64 ffma2(u64 a, u64 b, u64 c) {
    u64 d; asm("fma.rn.f32x2 %0, %1, %2, %3;" : "=l"(d) : "l"(a), "l"(b), "l"(c)); return d;
}
__device__ __forceinline__ u64 add2(u64 a, u64 b) {
    u64 d; asm("add.rn.f32x2 %0, %1, %2;" : "=l"(d) : "l"(a), "l"(b)); return d;
}
__device__ __forceinline__ u64 mul2(u64 a, u64 b) {
    u64 d; asm("mul.rn.f32x2 %0, %1, %2;" : "=l"(d) : "l"(a), "l"(b)); return d;
}

__device__ __forceinline__ float fast_sigmoid(float x) {
    return __fdividef(1.0f, 1.0f + __expf(-x));
}

__device__ __forceinline__ float colony_act(int c, float x) {
    switch (c) {
        case 0: return fmaxf(x, 0.0f);
        case 1: { float e = __expf(2.0f * x); return 1.0f - __fdividef(2.0f, e + 1.0f); }
        case 2: return 0.5f * x * (1.0f + erff(x * 0.7071067811865476f));
        case 3: return x * fast_sigmoid(x);
        case 4: return fmaxf(x, 0.0f) + log1pf(__expf(-fabsf(x)));
        case 5: return fast_sigmoid(x);
        default: return fminf(fmaxf(x, -1.0f), 1.0f);
    }
}

// ============================================================================
// Kernel Z: transpose z [B][98] -> z_blk [blk][98][32]  (pure bandwidth)
// ============================================================================
__global__ void __launch_bounds__(256, 4)
colony_kz(const float* __restrict__ z)
{
    __shared__ float tile[32 * 99];
    const int blk = blockIdx.x;
    const float* src = z + (size_t)blk * 3136;
    for (int idx = threadIdx.x; idx < 3136; idx += 256) {
        int b = idx / 98, q = idx % 98;
        tile[b * 99 + q] = src[idx];
    }
    __syncthreads();
    float* dst = g_z_blk + (size_t)blk * 3136;
    for (int idx = threadIdx.x; idx < 3136; idx += 256) {
        int q = idx >> 5, bb = idx & 31;
        dst[idx] = tile[bb * 99 + q];
    }
}

// ============================================================================
// Kernel 1: lane = batch; 8 warps, row 76 (smem 187KB < R12's 199KB, +1 warp).
// Inner code identical to proven R12 k1.
// ============================================================================
#define K1_WARPS 8
#define K1_THREADS (K1_WARPS * 32)
#define K1_ROW 76    // h [0,64) | conf [64,71) | pad ; 76/4=19 odd -> conflict-free float4
#define K1_WSZ (27344 + K1_WARPS * 32 * K1_ROW)
#define K1_SMEM (K1_WSZ * 4)

__global__ void __launch_bounds__(K1_THREADS, 1)
colony_k1(const float* __restrict__ gen_W1, const float* __restrict__ gen_b1,
          const float* __restrict__ gen_g,  const float* __restrict__ gen_be,
          const float* __restrict__ gen_W2, const float* __restrict__ gen_b2,
          const float* __restrict__ cf_W1,  const float* __restrict__ cf_b1,
          const float* __restrict__ cf_W2,  const float* __restrict__ cf_b2,
          const float* __restrict__ gw,     const float* __restrict__ gb,
          float* __restrict__ out_conf)
{
    extern __shared__ __align__(16) float sm[];
    float* sW1  = sm;            // 6272  [7][14][64]
    float* sb1  = sW1  + 6272;   // 448
    float* sg   = sb1  + 448;    // 448
    float* sbe  = sg   + 448;    // 448
    float* sW2  = sbe  + 448;    // 14336 [7][64][32]
    float* sb2  = sW2  + 14336;  // 224
    float* scW1 = sb2  + 224;    // 3136  [7][14][32]
    float* scb1 = scW1 + 3136;   // 224
    float* scW2 = scb1 + 224;    // 224
    float* scb2 = scW2 + 224;    // 8
    float* sgWT = scb2 + 8;      // 1568  transposed [7][224]
    float* sgb  = sgWT + 1568;   // 8
    float* rows = sgb  + 8;

    const int tid = threadIdx.x;
    for (int i = tid; i < 6272;  i += blockDim.x) sW1[i]  = gen_W1[i];
    for (int i = tid; i < 448;   i += blockDim.x) sb1[i]  = gen_b1[i];
    for (int i = tid; i < 448;   i += blockDim.x) sg[i]   = gen_g[i];
    for (int i = tid; i < 448;   i += blockDim.x) sbe[i]  = gen_be[i];
    for (int i = tid; i < 14336; i += blockDim.x) sW2[i]  = gen_W2[i];
    for (int i = tid; i < 224;   i += blockDim.x) sb2[i]  = gen_b2[i];
    for (int i = tid; i < 3136;  i += blockDim.x) scW1[i] = cf_W1[i];
    for (int i = tid; i < 224;   i += blockDim.x) scb1[i] = cf_b1[i];
    for (int i = tid; i < 224;   i += blockDim.x) scW2[i] = cf_W2[i];
    for (int i = tid; i < 7;     i += blockDim.x) scb2[i] = cf_b2[i];
    for (int i = tid; i < 1568;  i += blockDim.x) {
        int l = i / 224, d = i % 224;
        sgWT[i] = gw[d * 7 + l];
    }
    for (int i = tid; i < 7;     i += blockDim.x) sgb[i]  = gb[i];
    __syncthreads();

    const int wid  = tid >> 5;
    const int lane = tid & 31;
    float* myrow = rows + (wid * 32 + lane) * K1_ROW;

    const int gwarp = blockIdx.x * K1_WARPS + wid;
    const int nwarp = gridDim.x * K1_WARPS;

    for (int blk = gwarp; blk < NBLK; blk += nwarp) {
        const int b = blk * 32 + lane;
        u64 gacc[7];
#pragma unroll
        for (int l = 0; l < 7; l++) gacc[l] = 0ull;

        for (int c = 0; c < NL; c++) {
            float x[14];
            const float* zb = g_z_blk + (size_t)blk * 3136 + c * 14 * 32 + lane;
#pragma unroll
            for (int q = 0; q < 14; q++) x[q] = zb[q * 32];

            // ---- stage 1: h = x @ W1 + b1, two 32-col chunks ----
            float s1 = 0.0f, s2 = 0.0f;
            for (int chunk = 0; chunk < 2; chunk++) {
                u64 h[16];
                {
                    const ulonglong2* bp = (const ulonglong2*)(sb1 + c * 64 + chunk * 32);
#pragma unroll
                    for (int k = 0; k < 8; k++) {
                        ulonglong2 bv = bp[k];
                        h[2 * k] = bv.x; h[2 * k + 1] = bv.y;
                    }
                }
                const float* Wb = sW1 + c * (14 * 64) + chunk * 32;
#pragma unroll
                for (int q = 0; q < 14; q++) {
                    u64 xd = dup2(x[q]);
                    const ulonglong2* wr = (const ulonglong2*)(Wb + q * 64);
#pragma unroll
                    for (int jj = 0; jj < 8; jj++) {
                        ulonglong2 w = wr[jj];
                        h[2 * jj]     = ffma2(xd, w.x, h[2 * jj]);
                        h[2 * jj + 1] = ffma2(xd, w.y, h[2 * jj + 1]);
                    }
                }
                u64 sp = h[0], qp = mul2(h[0], h[0]);
#pragma unroll
                for (int k = 1; k < 16; k++) {
                    sp = add2(sp, h[k]);
                    qp = ffma2(h[k], h[k], qp);
                }
                float2 fs = unpack2(sp), fq = unpack2(qp);
                s1 += fs.x + fs.y;
                s2 += fq.x + fq.y;
                float4* hst = (float4*)(myrow + chunk * 32);
#pragma unroll
                for (int k = 0; k < 8; k++) {
                    float2 lo = unpack2(h[2 * k]);
                    float2 hi = unpack2(h[2 * k + 1]);
                    hst[k] = make_float4(lo.x, lo.y, hi.x, hi.y);
                }
            }
            const float m  = s1 * (1.0f / 64.0f);
            const float var = fmaxf(s2 * (1.0f / 64.0f) - m * m, 0.0f);
            const float iv  = rsqrtf(var + 1e-5f);

            // ---- stage 2: t = ACT(LN(h)) @ W2 + b2 (fused) ----
            u64 t[16];
            {
                const ulonglong2* bp = (const ulonglong2*)(sb2 + c * 32);
#pragma unroll
                for (int k = 0; k < 8; k++) {
                    ulonglong2 bv = bp[k];
                    t[2 * k] = bv.x; t[2 * k + 1] = bv.y;
                }
            }
            for (int r0 = 0; r0 < 16; r0++) {
                float4 hv = ((const float4*)myrow)[r0];
                float4 gv = *(const float4*)(sg + c * 64 + r0 * 4);
                float4 bv = *(const float4*)(sbe + c * 64 + r0 * 4);
#pragma unroll
                for (int r = 0; r < 4; r++) {
                    float hh = (r == 0) ? hv.x : (r == 1) ? hv.y : (r == 2) ? hv.z : hv.w;
                    float gg = (r == 0) ? gv.x : (r == 1) ? gv.y : (r == 2) ? gv.z : gv.w;
                    float bb = (r == 0) ? bv.x : (r == 1) ? bv.y : (r == 2) ? bv.z : bv.w;
                    float av = colony_act(c, fmaf((hh - m) * iv, gg, bb));
                    u64 ad = dup2(av);
                    const ulonglong2* wr = (const ulonglong2*)(sW2 + c * 2048 + (r0 * 4 + r) * 32);
#pragma unroll
                    for (int k = 0; k < 8; k++) {
                        ulonglong2 w = wr[k];
                        t[2 * k]     = ffma2(ad, w.x, t[2 * k]);
                        t[2 * k + 1] = ffma2(ad, w.y, t[2 * k + 1]);
                    }
                }
            }
            // ---- l2norm ----
            u64 nq = mul2(t[0], t[0]);
#pragma unroll
            for (int k = 1; k < 16; k++) nq = ffma2(t[k], t[k], nq);
            float2 nf = unpack2(nq);
            u64 nd = dup2(rsqrtf(fmaxf(nf.x + nf.y, 1e-24f)));
#pragma unroll
            for (int k = 0; k < 16; k++) t[k] = mul2(t[k], nd);

            // ---- store blocked traces ----
            {
                float* tb = g_traces_blk + (size_t)blk * 7168 + c * 1024 + lane;
#pragma unroll
                for (int k = 0; k < 16; k++) {
                    float2 f = unpack2(t[k]);
                    tb[(2 * k) * 32]     = f.x;
                    tb[(2 * k + 1) * 32] = f.y;
                }
            }
            // ---- accumulate gates ----
#pragma unroll
            for (int l = 0; l < 7; l++) {
                const ulonglong2* gp = (const ulonglong2*)(sgWT + l * 224 + c * 32);
                u64 acc = gacc[l];
#pragma unroll
                for (int k = 0; k < 8; k++) {
                    ulonglong2 w = gp[k];
                    acc = ffma2(t[2 * k], w.x, acc);
                    acc = ffma2(t[2 * k + 1], w.y, acc);
                }
                gacc[l] = acc;
            }
            // ---- confidence head ----
            {
                u64 hc[16];
                const ulonglong2* bp = (const ulonglong2*)(scb1 + c * 32);
#pragma unroll
                for (int k = 0; k < 8; k++) {
                    ulonglong2 bv = bp[k];
                    hc[2 * k] = bv.x; hc[2 * k + 1] = bv.y;
                }
                const float* cw = scW1 + c * 448;
#pragma unroll
                for (int q = 0; q < 14; q++) {
                    u64 xd = dup2(x[q]);
                    const ulonglong2* wr = (const ulonglong2*)(cw + q * 32);
#pragma unroll
                    for (int k = 0; k < 8; k++) {
                        ulonglong2 w = wr[k];
                        hc[2 * k]     = ffma2(xd, w.x, hc[2 * k]);
                        hc[2 * k + 1] = ffma2(xd, w.y, hc[2 * k + 1]);
                    }
                }
                float dacc = 0.0f;
                const u64* w2p = (const u64*)(scW2 + c * 32);
#pragma unroll
                for (int k = 0; k < 16; k++) {
                    float2 hh = unpack2(hc[k]);
                    float2 ww = unpack2(w2p[k]);
                    dacc = fmaf(fmaxf(hh.x, 0.0f), ww.x, dacc);
                    dacc = fmaf(fmaxf(hh.y, 0.0f), ww.y, dacc);
                }
                myrow[64 + c] = fast_sigmoid(dacc + scb2[c]);
            }
        }

        // ---- gates final + stores ----
        float gate[7];
#pragma unroll
        for (int l = 0; l < 7; l++) {
            float2 f = unpack2(gacc[l]);
            gate[l] = fast_sigmoid(f.x + f.y + sgb[l]);
            g_gates_T[(size_t)l * B_TOTAL + b] = gate[l];
        }
        float cf[7];
#pragma unroll
        for (int i = 0; i < 7; i++) cf[i] = myrow[64 + i];
#pragma unroll
        for (int j = 0; j < 21; j++) {
            float gl = gate[j / 3];
            float v = (gl >= 0.3f) ? cf[FSRC[j]] * cf[FPAR[j]] * gl : 0.0f;
            out_conf[(size_t)b * 21 + j] = v;
        }
    }
}

// ============================================================================
// Kernel 2: EXACT round-12 version (10 warps, row 132) — proven 427us.
// ============================================================================
#define K2_WARPS 10
#define K2_THREADS (K2_WARPS * 32)
#define K2_BLK_PER_LINE 21
#define K2_GRID (NL * K2_BLK_PER_LINE)
#define K2_ROW 132
#define K2_WSZ (6368 + K2_WARPS * 32 * K2_ROW)
#define K2_SMEM (K2_WSZ * 4)

__global__ void __launch_bounds__(K2_THREADS, 1)
colony_k2(const float* __restrict__ cW1, const float* __restrict__ cb1,
          const float* __restrict__ cg,  const float* __restrict__ cbe,
          const float* __restrict__ cW2, const float* __restrict__ cb2,
          float* __restrict__ out)
{
    extern __shared__ __align__(16) float sm[];
    float* sW1 = sm;
    float* sW2 = sW1 + 4096;
    float* sb1 = sW2 + 2048;
    float* sgl = sb1 + 64;
    float* sbe = sgl + 64;
    float* sb2 = sbe + 64;
    float* stile = sb2 + 32;

    const int line = blockIdx.x % NL;
    const int tid = threadIdx.x;
    {
        const float* w1 = cW1 + line * 4096;
        const float* w2 = cW2 + line * 2048;
        for (int i = tid; i < 4096; i += blockDim.x) sW1[i] = w1[i];
        for (int i = tid; i < 2048; i += blockDim.x) sW2[i] = w2[i];
        if (tid < 64) {
            sb1[tid] = cb1[line * 64 + tid];
            sgl[tid] = cg[line * 64 + tid];
            sbe[tid] = cbe[line * 64 + tid];
        }
        if (tid < 32) sb2[tid] = cb2[line * 32 + tid];
    }
    __syncthreads();

    const int wid  = tid >> 5;
    const int lane = tid & 31;
    float* myrow = stile + (wid * 32 + lane) * K2_ROW;
    float* wrows = stile + (wid * 32) * K2_ROW;

    const int col0 = FSRC[line * 3 + 0];
    const int col1 = FSRC[line * 3 + 1];
    const int col2 = FSRC[line * 3 + 2];

    const int lwarp = (blockIdx.x / NL) * K2_WARPS + wid;
    const int nlw   = K2_BLK_PER_LINE * K2_WARPS;
    const int ngroups = B_TOTAL / 64;

    for (int g = lwarp; g < ngroups; g += nlw) {
        const int blkA = 2 * g, blkB = 2 * g + 1;
        const int bA = g * 64 + lane;
        const int bB = bA + 32;

        const float gateA = g_gates_T[(size_t)line * B_TOTAL + bA];
        const float gateB = g_gates_T[(size_t)line * B_TOTAL + bB];
        const float sclA = (gateA >= 0.3f) ? gateA : 0.0f;
        const float sclB = (gateB >= 0.3f) ? gateB : 0.0f;

        for (int p = 0; p < 3; p++) {
            const int cS = (p == 0) ? col0 : (p == 1) ? col1 : col2;
            const int cP = (p == 0) ? col1 : (p == 1) ? col2 : col0;

            float s1A = 0.0f, s2A = 0.0f, s1B = 0.0f, s2B = 0.0f;
            for (int chunk = 0; chunk < 2; chunk++) {
                u64 hA[16], hB[16];
                {
                    const ulonglong2* bp = (const ulonglong2*)(sb1 + chunk * 32);
#pragma unroll
                    for (int k = 0; k < 8; k++) {
                        ulonglong2 bv = bp[k];
                        hA[2 * k] = bv.x; hA[2 * k + 1] = bv.y;
                        hB[2 * k] = bv.x; hB[2 * k + 1] = bv.y;
                    }
                }
                for (int half = 0; half < 2; half++) {
                    const int colony = half ? cP : cS;
                    const float* xA = g_traces_blk + (size_t)blkA * 7168 + colony * 1024 + lane;
                    const float* xB = g_traces_blk + (size_t)blkB * 7168 + colony * 1024 + lane;
                    const float* Wb = sW1 + half * 2048 + chunk * 32;
#pragma unroll 8
                    for (int i = 0; i < 32; i++) {
                        u64 aD = dup2(xA[i * 32]);
                        u64 bD = dup2(xB[i * 32]);
                        const ulonglong2* wr = (const ulonglong2*)(Wb + i * 64);
#pragma unroll
                        for (int jj = 0; jj < 8; jj++) {
                            ulonglong2 w = wr[jj];
                            hA[2 * jj]     = ffma2(aD, w.x, hA[2 * jj]);
                            hA[2 * jj + 1] = ffma2(aD, w.y, hA[2 * jj + 1]);
                            hB[2 * jj]     = ffma2(bD, w.x, hB[2 * jj]);
                            hB[2 * jj + 1] = ffma2(bD, w.y, hB[2 * jj + 1]);
                        }
                    }
                }
                {
                    u64 sAp = hA[0], qAp = mul2(hA[0], hA[0]);
                    u64 sBp = hB[0], qBp = mul2(hB[0], hB[0]);
#pragma unroll
                    for (int k = 1; k < 16; k++) {
                        sAp = add2(sAp, hA[k]); qAp = ffma2(hA[k], hA[k], qAp);
                        sBp = add2(sBp, hB[k]); qBp = ffma2(hB[k], hB[k], qBp);
                    }
                    float2 a1 = unpack2(sAp), a2 = unpack2(qAp);
                    float2 b1 = unpack2(sBp), b2 = unpack2(qBp);
                    s1A += a1.x + a1.y;  s2A += a2.x + a2.y;
                    s1B += b1.x + b1.y;  s2B += b2.x + b2.y;
                }
                {
                    float4* hstA = (float4*)(myrow + chunk * 32);
                    float4* hstB = (float4*)(myrow + 64 + chunk * 32);
#pragma unroll
                    for (int k = 0; k < 8; k++) {
                        float2 lo = unpack2(hA[2 * k]);
                        float2 hi = unpack2(hA[2 * k + 1]);
                        hstA[k] = make_float4(lo.x, lo.y, hi.x, hi.y);
                        lo = unpack2(hB[2 * k]);
                        hi = unpack2(hB[2 * k + 1]);
                        hstB[k] = make_float4(lo.x, lo.y, hi.x, hi.y);
                    }
                }
            }
            const float mA = s1A * (1.0f / 64.0f);
            const float mB = s1B * (1.0f / 64.0f);
            const float ivA = rsqrtf(fmaxf(s2A * (1.0f / 64.0f) - mA * mA, 0.0f) + 1e-5f);
            const float ivB = rsqrtf(fmaxf(s2B * (1.0f / 64.0f) - mB * mB, 0.0f) + 1e-5f);

            u64 tA[16], tB[16];
            {
                const ulonglong2* bp = (const ulonglong2*)sb2;
#pragma unroll
                for (int k = 0; k < 8; k++) {
                    ulonglong2 bv = bp[k];
                    tA[2 * k] = bv.x; tA[2 * k + 1] = bv.y;
                    tB[2 * k] = bv.x; tB[2 * k + 1] = bv.y;
                }
            }
#pragma unroll 4
            for (int r0 = 0; r0 < 16; r0++) {
                float4 hvA = ((const float4*)myrow)[r0];
                float4 hvB = ((const float4*)(myrow + 64))[r0];
                float4 gv = ((const float4*)sgl)[r0];
                float4 bv = ((const float4*)sbe)[r0];
#pragma unroll
                for (int r = 0; r < 4; r++) {
                    float hA1 = (r == 0) ? hvA.x : (r == 1) ? hvA.y : (r == 2) ? hvA.z : hvA.w;
                    float hB1 = (r == 0) ? hvB.x : (r == 1) ? hvB.y : (r == 2) ? hvB.z : hvB.w;
                    float gw1 = (r == 0) ? gv.x : (r == 1) ? gv.y : (r == 2) ? gv.z : gv.w;
                    float bw1 = (r == 0) ? bv.x : (r == 1) ? bv.y : (r == 2) ? bv.z : bv.w;
                    float aAv = fmaxf(fmaf((hA1 - mA) * ivA, gw1, bw1), 0.0f);
                    float aBv = fmaxf(fmaf((hB1 - mB) * ivB, gw1, bw1), 0.0f);
                    u64 aD = dup2(aAv);
                    u64 bD = dup2(aBv);
                    const ulonglong2* wr = (const ulonglong2*)(sW2 + (r0 * 4 + r) * 32);
#pragma unroll
                    for (int k = 0; k < 8; k++) {
                        ulonglong2 w = wr[k];
                        tA[2 * k]     = ffma2(aD, w.x, tA[2 * k]);
                        tA[2 * k + 1] = ffma2(aD, w.y, tA[2 * k + 1]);
                        tB[2 * k]     = ffma2(bD, w.x, tB[2 * k]);
                        tB[2 * k + 1] = ffma2(bD, w.y, tB[2 * k + 1]);
                    }
                }
            }
            {
                u64 nqA = mul2(tA[0], tA[0]);
                u64 nqB = mul2(tB[0], tB[0]);
#pragma unroll
                for (int k = 1; k < 16; k++) {
                    nqA = ffma2(tA[k], tA[k], nqA);
                    nqB = ffma2(tB[k], tB[k], nqB);
                }
                float2 fa = unpack2(nqA), fb = unpack2(nqB);
                u64 scA2 = dup2(sclA * rsqrtf(fmaxf(fa.x + fa.y, 1e-24f)));
                u64 scB2 = dup2(sclB * rsqrtf(fmaxf(fb.x + fb.y, 1e-24f)));
                float4* oA = (float4*)myrow;
                float4* oB = (float4*)(myrow + 64);
#pragma unroll
                for (int k = 0; k < 8; k++) {
                    float2 o0 = unpack2(mul2(tA[2 * k], scA2));
                    float2 o1 = unpack2(mul2(tA[2 * k + 1], scA2));
                    oA[k] = make_float4(o0.x, o0.y, o1.x, o1.y);
                    o0 = unpack2(mul2(tB[2 * k], scB2));
                    o1 = unpack2(mul2(tB[2 * k + 1], scB2));
                    oB[k] = make_float4(o0.x, o0.y, o1.x, o1.y);
                }
            }
            __syncwarp();

            for (int k = lane; k < 256; k += 32) {
                int m = k >> 3, j = k & 7;
                const float* src = wrows + m * K2_ROW;
                float4 vA = *(const float4*)(src + j * 4);
                float4 vB = *(const float4*)(src + 64 + j * 4);
                size_t rowA = (((size_t)(g * 64 + m) * 7 + line) * 3 + p) * 32;
                size_t rowB = (((size_t)(g * 64 + 32 + m) * 7 + line) * 3 + p) * 32;
                *(float4*)(out + rowA + j * 4) = vA;
                *(float4*)(out + rowB + j * 4) = vB;
            }
            __syncwarp();
        }
    }
}

// ============================================================================
extern "C" void kernel_launch(void* const* d_in, const int* in_sizes, int n_in,
                              void* d_out, int out_size)
{
    const float* z      = (const float*)d_in[0];
    const float* gen_W1 = (const float*)d_in[1];
    const float* gen_b1 = (const float*)d_in[2];
    const float* gen_g  = (const float*)d_in[3];
    const float* gen_be = (const float*)d_in[4];
    const float* gen_W2 = (const float*)d_in[5];
    const float* gen_b2 = (const float*)d_in[6];
    const float* cf_W1  = (const float*)d_in[7];
    const float* cf_b1  = (const float*)d_in[8];
    const float* cf_W2  = (const float*)d_in[9];
    const float* cf_b2  = (const float*)d_in[10];
    const float* g_W    = (const float*)d_in[11];
    const float* g_b    = (const float*)d_in[12];
    const float* c_W1   = (const float*)d_in[13];
    const float* c_b1   = (const float*)d_in[14];
    const float* c_g    = (const float*)d_in[15];
    const float* c_be   = (const float*)d_in[16];
    const float* c_W2   = (const float*)d_in[17];
    const float* c_b2   = (const float*)d_in[18];

    float* out      = (float*)d_out;                       // composed [B,7,3,32]
    float* out_conf = out + (size_t)B_TOTAL * 672;         // comp_conf [B,7,3]

    cudaFuncSetAttribute(colony_k1, cudaFuncAttributeMaxDynamicSharedMemorySize, K1_SMEM);
    cudaFuncSetAttribute(colony_k2, cudaFuncAttributeMaxDynamicSharedMemorySize, K2_SMEM);

    colony_kz<<<NBLK, 256>>>(z);
    colony_k1<<<148, K1_THREADS, K1_SMEM>>>(gen_W1, gen_b1, gen_g, gen_be, gen_W2, gen_b2,
                                            cf_W1, cf_b1, cf_W2, cf_b2, g_W, g_b, out_conf);
    colony_k2<<<K2_GRID, K2_THREADS, K2_SMEM>>>(c_W1, c_b1, c_g, c_be, c_W2, c_b2, out);
}

// round 16
// speedup vs baseline: 1.2630x; 1.0269x over previous
#include <cuda_runtime.h>
#include <math.h>

#define B_TOTAL 65536
#define NBLK (B_TOTAL / 32)
#define NL 7

typedef unsigned long long u64;

// ---- scratch (static device globals) ----
__device__ __align__(16) float g_traces_blk[(size_t)B_TOTAL * 224];   // [blk][c][d][32]
__device__ __align__(16) float g_gates_T[(size_t)NL * B_TOTAL];       // [line][b]

__constant__ int FSRC[21] = {0,1,2, 0,3,4, 0,5,6, 1,3,5, 1,4,6, 2,3,6, 2,4,5};
__constant__ int FPAR[21] = {1,2,0, 3,4,0, 5,6,0, 3,5,1, 4,6,1, 3,6,2, 4,5,2};

__device__ __forceinline__ u64 pack2(float x, float y) {
    u64 r; asm("mov.b64 %0, {%1,%2};" : "=l"(r) : "f"(x), "f"(y)); return r;
}
__device__ __forceinline__ float2 unpack2(u64 v) {
    float2 r; asm("mov.b64 {%0,%1}, %2;" : "=f"(r.x), "=f"(r.y) : "l"(v)); return r;
}
__device__ __forceinline__ u64 dup2(float x) { return pack2(x, x); }
__device__ __forceinline__ u64 ffma2(u64 a, u64 b, u64 c) {
    u64 d; asm("fma.rn.f32x2 %0, %1, %2, %3;" : "=l"(d) : "l"(a), "l"(b), "l"(c)); return d;
}
__device__ __forceinline__ u64 add2(u64 a, u64 b) {
    u64 d; asm("add.rn.f32x2 %0, %1, %2;" : "=l"(d) : "l"(a), "l"(b)); return d;
}
__device__ __forceinline__ u64 mul2(u64 a, u64 b) {
    u64 d; asm("mul.rn.f32x2 %0, %1, %2;" : "=l"(d) : "l"(a), "l"(b)); return d;
}

__device__ __forceinline__ float fast_sigmoid(float x) {
    return __fdividef(1.0f, 1.0f + __expf(-x));
}

__device__ __forceinline__ float colony_act(int c, float x) {
    switch (c) {
        case 0: return fmaxf(x, 0.0f);
        case 1: { float e = __expf(2.0f * x); return 1.0f - __fdividef(2.0f, e + 1.0f); }
        case 2: return 0.5f * x * (1.0f + erff(x * 0.7071067811865476f));
        case 3: return x * fast_sigmoid(x);
        case 4: return fmaxf(x, 0.0f) + log1pf(__expf(-fabsf(x)));
        case 5: return fast_sigmoid(x);
        default: return fminf(fmaxf(x, -1.0f), 1.0f);
    }
}

// ============================================================================
// Kernel 1: lane = batch; 7 warps, row 76; z-transpose FUSED via per-warp tile.
// ============================================================================
#define K1_WARPS 7
#define K1_THREADS (K1_WARPS * 32)
#define K1_ROW 76    // h [0,64) | conf [64,71) | pad ; 76/4=19 odd -> conflict-free float4
#define K1_ZT 464    // z tile: 14 rows * 33 cols = 462, pad 464
#define K1_WSZ (27344 + K1_WARPS * 32 * K1_ROW + K1_WARPS * K1_ZT)
#define K1_SMEM (K1_WSZ * 4)

__global__ void __launch_bounds__(K1_THREADS, 1)
colony_k1(const float* __restrict__ z,
          const float* __restrict__ gen_W1, const float* __restrict__ gen_b1,
          const float* __restrict__ gen_g,  const float* __restrict__ gen_be,
          const float* __restrict__ gen_W2, const float* __restrict__ gen_b2,
          const float* __restrict__ cf_W1,  const float* __restrict__ cf_b1,
          const float* __restrict__ cf_W2,  const float* __restrict__ cf_b2,
          const float* __restrict__ gw,     const float* __restrict__ gb,
          float* __restrict__ out_conf)
{
    extern __shared__ __align__(16) float sm[];
    float* sW1  = sm;            // 6272  [7][14][64]
    float* sb1  = sW1  + 6272;   // 448
    float* sg   = sb1  + 448;    // 448
    float* sbe  = sg   + 448;    // 448
    float* sW2  = sbe  + 448;    // 14336 [7][64][32]
    float* sb2  = sW2  + 14336;  // 224
    float* scW1 = sb2  + 224;    // 3136  [7][14][32]
    float* scb1 = scW1 + 3136;   // 224
    float* scW2 = scb1 + 224;    // 224
    float* scb2 = scW2 + 224;    // 8
    float* sgWT = scb2 + 8;      // 1568  transposed [7][224]
    float* sgb  = sgWT + 1568;   // 8
    float* rows = sgb  + 8;                       // per-lane private rows
    float* ztiles = rows + K1_WARPS * 32 * K1_ROW; // per-warp z tiles [14][33]

    const int tid = threadIdx.x;
    for (int i = tid; i < 6272;  i += blockDim.x) sW1[i]  = gen_W1[i];
    for (int i = tid; i < 448;   i += blockDim.x) sb1[i]  = gen_b1[i];
    for (int i = tid; i < 448;   i += blockDim.x) sg[i]   = gen_g[i];
    for (int i = tid; i < 448;   i += blockDim.x) sbe[i]  = gen_be[i];
    for (int i = tid; i < 14336; i += blockDim.x) sW2[i]  = gen_W2[i];
    for (int i = tid; i < 224;   i += blockDim.x) sb2[i]  = gen_b2[i];
    for (int i = tid; i < 3136;  i += blockDim.x) scW1[i] = cf_W1[i];
    for (int i = tid; i < 224;   i += blockDim.x) scb1[i] = cf_b1[i];
    for (int i = tid; i < 224;   i += blockDim.x) scW2[i] = cf_W2[i];
    for (int i = tid; i < 7;     i += blockDim.x) scb2[i] = cf_b2[i];
    for (int i = tid; i < 1568;  i += blockDim.x) {
        int l = i / 224, d = i % 224;
        sgWT[i] = gw[d * 7 + l];
    }
    for (int i = tid; i < 7;     i += blockDim.x) sgb[i]  = gb[i];
    __syncthreads();

    const int wid  = tid >> 5;
    const int lane = tid & 31;
    float* myrow = rows + (wid * 32 + lane) * K1_ROW;
    float* zt    = ztiles + wid * K1_ZT;

    const int gwarp = blockIdx.x * K1_WARPS + wid;
    const int nwarp = gridDim.x * K1_WARPS;

    for (int blk = gwarp; blk < NBLK; blk += nwarp) {
        const int b = blk * 32 + lane;
        u64 gacc[7];
#pragma unroll
        for (int l = 0; l < 7; l++) gacc[l] = 0ull;

        for (int c = 0; c < NL; c++) {
            // ---- fused z transpose: warp stages [32 batches][14] -> zt[q][m] ----
            {
                const float* zsrc = z + (size_t)blk * 3136 + c * 14;
#pragma unroll
                for (int k0 = 0; k0 < 14; k0++) {
                    int k = k0 * 32 + lane;          // 448 elements
                    int m = k / 14, q = k - m * 14;
                    zt[q * 33 + m] = zsrc[m * 98 + q];
                }
                __syncwarp();
            }
            float x[14];
#pragma unroll
            for (int q = 0; q < 14; q++) x[q] = zt[q * 33 + lane];
            __syncwarp();

            // ---- stage 1: h = x @ W1 + b1, two 32-col chunks ----
            float s1 = 0.0f, s2 = 0.0f;
            for (int chunk = 0; chunk < 2; chunk++) {
                u64 h[16];
                {
                    const ulonglong2* bp = (const ulonglong2*)(sb1 + c * 64 + chunk * 32);
#pragma unroll
                    for (int k = 0; k < 8; k++) {
                        ulonglong2 bv = bp[k];
                        h[2 * k] = bv.x; h[2 * k + 1] = bv.y;
                    }
                }
                const float* Wb = sW1 + c * (14 * 64) + chunk * 32;
#pragma unroll
                for (int q = 0; q < 14; q++) {
                    u64 xd = dup2(x[q]);
                    const ulonglong2* wr = (const ulonglong2*)(Wb + q * 64);
#pragma unroll
                    for (int jj = 0; jj < 8; jj++) {
                        ulonglong2 w = wr[jj];
                        h[2 * jj]     = ffma2(xd, w.x, h[2 * jj]);
                        h[2 * jj + 1] = ffma2(xd, w.y, h[2 * jj + 1]);
                    }
                }
                u64 sp = h[0], qp = mul2(h[0], h[0]);
#pragma unroll
                for (int k = 1; k < 16; k++) {
                    sp = add2(sp, h[k]);
                    qp = ffma2(h[k], h[k], qp);
                }
                float2 fs = unpack2(sp), fq = unpack2(qp);
                s1 += fs.x + fs.y;
                s2 += fq.x + fq.y;
                float4* hst = (float4*)(myrow + chunk * 32);
#pragma unroll
                for (int k = 0; k < 8; k++) {
                    float2 lo = unpack2(h[2 * k]);
                    float2 hi = unpack2(h[2 * k + 1]);
                    hst[k] = make_float4(lo.x, lo.y, hi.x, hi.y);
                }
            }
            const float m  = s1 * (1.0f / 64.0f);
            const float var = fmaxf(s2 * (1.0f / 64.0f) - m * m, 0.0f);
            const float iv  = rsqrtf(var + 1e-5f);

            // ---- stage 2: t = ACT(LN(h)) @ W2 + b2 (fused) ----
            u64 t[16];
            {
                const ulonglong2* bp = (const ulonglong2*)(sb2 + c * 32);
#pragma unroll
                for (int k = 0; k < 8; k++) {
                    ulonglong2 bv = bp[k];
                    t[2 * k] = bv.x; t[2 * k + 1] = bv.y;
                }
            }
            for (int r0 = 0; r0 < 16; r0++) {
                float4 hv = ((const float4*)myrow)[r0];
                float4 gv = *(const float4*)(sg + c * 64 + r0 * 4);
                float4 bv = *(const float4*)(sbe + c * 64 + r0 * 4);
#pragma unroll
                for (int r = 0; r < 4; r++) {
                    float hh = (r == 0) ? hv.x : (r == 1) ? hv.y : (r == 2) ? hv.z : hv.w;
                    float gg = (r == 0) ? gv.x : (r == 1) ? gv.y : (r == 2) ? gv.z : gv.w;
                    float bb = (r == 0) ? bv.x : (r == 1) ? bv.y : (r == 2) ? bv.z : bv.w;
                    float av = colony_act(c, fmaf((hh - m) * iv, gg, bb));
                    u64 ad = dup2(av);
                    const ulonglong2* wr = (const ulonglong2*)(sW2 + c * 2048 + (r0 * 4 + r) * 32);
#pragma unroll
                    for (int k = 0; k < 8; k++) {
                        ulonglong2 w = wr[k];
                        t[2 * k]     = ffma2(ad, w.x, t[2 * k]);
                        t[2 * k + 1] = ffma2(ad, w.y, t[2 * k + 1]);
                    }
                }
            }
            // ---- l2norm ----
            u64 nq = mul2(t[0], t[0]);
#pragma unroll
            for (int k = 1; k < 16; k++) nq = ffma2(t[k], t[k], nq);
            float2 nf = unpack2(nq);
            u64 nd = dup2(rsqrtf(fmaxf(nf.x + nf.y, 1e-24f)));
#pragma unroll
            for (int k = 0; k < 16; k++) t[k] = mul2(t[k], nd);

            // ---- store blocked traces ----
            {
                float* tb = g_traces_blk + (size_t)blk * 7168 + c * 1024 + lane;
#pragma unroll
                for (int k = 0; k < 16; k++) {
                    float2 f = unpack2(t[k]);
                    tb[(2 * k) * 32]     = f.x;
                    tb[(2 * k + 1) * 32] = f.y;
                }
            }
            // ---- accumulate gates ----
#pragma unroll
            for (int l = 0; l < 7; l++) {
                const ulonglong2* gp = (const ulonglong2*)(sgWT + l * 224 + c * 32);
                u64 acc = gacc[l];
#pragma unroll
                for (int k = 0; k < 8; k++) {
                    ulonglong2 w = gp[k];
                    acc = ffma2(t[2 * k], w.x, acc);
                    acc = ffma2(t[2 * k + 1], w.y, acc);
                }
                gacc[l] = acc;
            }
            // ---- confidence head ----
            {
                u64 hc[16];
                const ulonglong2* bp = (const ulonglong2*)(scb1 + c * 32);
#pragma unroll
                for (int k = 0; k < 8; k++) {
                    ulonglong2 bv = bp[k];
                    hc[2 * k] = bv.x; hc[2 * k + 1] = bv.y;
                }
                const float* cw = scW1 + c * 448;
#pragma unroll
                for (int q = 0; q < 14; q++) {
                    u64 xd = dup2(x[q]);
                    const ulonglong2* wr = (const ulonglong2*)(cw + q * 32);
#pragma unroll
                    for (int k = 0; k < 8; k++) {
                        ulonglong2 w = wr[k];
                        hc[2 * k]     = ffma2(xd, w.x, hc[2 * k]);
                        hc[2 * k + 1] = ffma2(xd, w.y, hc[2 * k + 1]);
                    }
                }
                float dacc = 0.0f;
                const u64* w2p = (const u64*)(scW2 + c * 32);
#pragma unroll
                for (int k = 0; k < 16; k++) {
                    float2 hh = unpack2(hc[k]);
                    float2 ww = unpack2(w2p[k]);
                    dacc = fmaf(fmaxf(hh.x, 0.0f), ww.x, dacc);
                    dacc = fmaf(fmaxf(hh.y, 0.0f), ww.y, dacc);
                }
                myrow[64 + c] = fast_sigmoid(dacc + scb2[c]);
            }
        }

        // ---- gates final + stores ----
        float gate[7];
#pragma unroll
        for (int l = 0; l < 7; l++) {
            float2 f = unpack2(gacc[l]);
            gate[l] = fast_sigmoid(f.x + f.y + sgb[l]);
            g_gates_T[(size_t)l * B_TOTAL + b] = gate[l];
        }
        float cf[7];
#pragma unroll
        for (int i = 0; i < 7; i++) cf[i] = myrow[64 + i];
#pragma unroll
        for (int j = 0; j < 21; j++) {
            float gl = gate[j / 3];
            float v = (gl >= 0.3f) ? cf[FSRC[j]] * cf[FPAR[j]] * gl : 0.0f;
            out_conf[(size_t)b * 21 + j] = v;
        }
    }
}

// ============================================================================
// Kernel 2: EXACT round-12 version (10 warps, row 132) — proven 427us.
// ============================================================================
#define K2_WARPS 10
#define K2_THREADS (K2_WARPS * 32)
#define K2_BLK_PER_LINE 21
#define K2_GRID (NL * K2_BLK_PER_LINE)
#define K2_ROW 132
#define K2_WSZ (6368 + K2_WARPS * 32 * K2_ROW)
#define K2_SMEM (K2_WSZ * 4)

__global__ void __launch_bounds__(K2_THREADS, 1)
colony_k2(const float* __restrict__ cW1, const float* __restrict__ cb1,
          const float* __restrict__ cg,  const float* __restrict__ cbe,
          const float* __restrict__ cW2, const float* __restrict__ cb2,
          float* __restrict__ out)
{
    extern __shared__ __align__(16) float sm[];
    float* sW1 = sm;
    float* sW2 = sW1 + 4096;
    float* sb1 = sW2 + 2048;
    float* sgl = sb1 + 64;
    float* sbe = sgl + 64;
    float* sb2 = sbe + 64;
    float* stile = sb2 + 32;

    const int line = blockIdx.x % NL;
    const int tid = threadIdx.x;
    {
        const float* w1 = cW1 + line * 4096;
        const float* w2 = cW2 + line * 2048;
        for (int i = tid; i < 4096; i += blockDim.x) sW1[i] = w1[i];
        for (int i = tid; i < 2048; i += blockDim.x) sW2[i] = w2[i];
        if (tid < 64) {
            sb1[tid] = cb1[line * 64 + tid];
            sgl[tid] = cg[line * 64 + tid];
            sbe[tid] = cbe[line * 64 + tid];
        }
        if (tid < 32) sb2[tid] = cb2[line * 32 + tid];
    }
    __syncthreads();

    const int wid  = tid >> 5;
    const int lane = tid & 31;
    float* myrow = stile + (wid * 32 + lane) * K2_ROW;
    float* wrows = stile + (wid * 32) * K2_ROW;

    const int col0 = FSRC[line * 3 + 0];
    const int col1 = FSRC[line * 3 + 1];
    const int col2 = FSRC[line * 3 + 2];

    const int lwarp = (blockIdx.x / NL) * K2_WARPS + wid;
    const int nlw   = K2_BLK_PER_LINE * K2_WARPS;
    const int ngroups = B_TOTAL / 64;

    for (int g = lwarp; g < ngroups; g += nlw) {
        const int blkA = 2 * g, blkB = 2 * g + 1;
        const int bA = g * 64 + lane;
        const int bB = bA + 32;

        const float gateA = g_gates_T[(size_t)line * B_TOTAL + bA];
        const float gateB = g_gates_T[(size_t)line * B_TOTAL + bB];
        const float sclA = (gateA >= 0.3f) ? gateA : 0.0f;
        const float sclB = (gateB >= 0.3f) ? gateB : 0.0f;

        for (int p = 0; p < 3; p++) {
            const int cS = (p == 0) ? col0 : (p == 1) ? col1 : col2;
            const int cP = (p == 0) ? col1 : (p == 1) ? col2 : col0;

            float s1A = 0.0f, s2A = 0.0f, s1B = 0.0f, s2B = 0.0f;
            for (int chunk = 0; chunk < 2; chunk++) {
                u64 hA[16], hB[16];
                {
                    const ulonglong2* bp = (const ulonglong2*)(sb1 + chunk * 32);
#pragma unroll
                    for (int k = 0; k < 8; k++) {
                        ulonglong2 bv = bp[k];
                        hA[2 * k] = bv.x; hA[2 * k + 1] = bv.y;
                        hB[2 * k] = bv.x; hB[2 * k + 1] = bv.y;
                    }
                }
                for (int half = 0; half < 2; half++) {
                    const int colony = half ? cP : cS;
                    const float* xA = g_traces_blk + (size_t)blkA * 7168 + colony * 1024 + lane;
                    const float* xB = g_traces_blk + (size_t)blkB * 7168 + colony * 1024 + lane;
                    const float* Wb = sW1 + half * 2048 + chunk * 32;
#pragma unroll 8
                    for (int i = 0; i < 32; i++) {
                        u64 aD = dup2(xA[i * 32]);
                        u64 bD = dup2(xB[i * 32]);
                        const ulonglong2* wr = (const ulonglong2*)(Wb + i * 64);
#pragma unroll
                        for (int jj = 0; jj < 8; jj++) {
                            ulonglong2 w = wr[jj];
                            hA[2 * jj]     = ffma2(aD, w.x, hA[2 * jj]);
                            hA[2 * jj + 1] = ffma2(aD, w.y, hA[2 * jj + 1]);
                            hB[2 * jj]     = ffma2(bD, w.x, hB[2 * jj]);
                            hB[2 * jj + 1] = ffma2(bD, w.y, hB[2 * jj + 1]);
                        }
                    }
                }
                {
                    u64 sAp = hA[0], qAp = mul2(hA[0], hA[0]);
                    u64 sBp = hB[0], qBp = mul2(hB[0], hB[0]);
#pragma unroll
                    for (int k = 1; k < 16; k++) {
                        sAp = add2(sAp, hA[k]); qAp = ffma2(hA[k], hA[k], qAp);
                        sBp = add2(sBp, hB[k]); qBp = ffma2(hB[k], hB[k], qBp);
                    }
                    float2 a1 = unpack2(sAp), a2 = unpack2(qAp);
                    float2 b1 = unpack2(sBp), b2 = unpack2(qBp);
                    s1A += a1.x + a1.y;  s2A += a2.x + a2.y;
                    s1B += b1.x + b1.y;  s2B += b2.x + b2.y;
                }
                {
                    float4* hstA = (float4*)(myrow + chunk * 32);
                    float4* hstB = (float4*)(myrow + 64 + chunk * 32);
#pragma unroll
                    for (int k = 0; k < 8; k++) {
                        float2 lo = unpack2(hA[2 * k]);
                        float2 hi = unpack2(hA[2 * k + 1]);
                        hstA[k] = make_float4(lo.x, lo.y, hi.x, hi.y);
                        lo = unpack2(hB[2 * k]);
                        hi = unpack2(hB[2 * k + 1]);
                        hstB[k] = make_float4(lo.x, lo.y, hi.x, hi.y);
                    }
                }
            }
            const float mA = s1A * (1.0f / 64.0f);
            const float mB = s1B * (1.0f / 64.0f);
            const float ivA = rsqrtf(fmaxf(s2A * (1.0f / 64.0f) - mA * mA, 0.0f) + 1e-5f);
            const float ivB = rsqrtf(fmaxf(s2B * (1.0f / 64.0f) - mB * mB, 0.0f) + 1e-5f);

            u64 tA[16], tB[16];
            {
                const ulonglong2* bp = (const ulonglong2*)sb2;
#pragma unroll
                for (int k = 0; k < 8; k++) {
                    ulonglong2 bv = bp[k];
                    tA[2 * k] = bv.x; tA[2 * k + 1] = bv.y;
                    tB[2 * k] = bv.x; tB[2 * k + 1] = bv.y;
                }
            }
#pragma unroll 4
            for (int r0 = 0; r0 < 16; r0++) {
                float4 hvA = ((const float4*)myrow)[r0];
                float4 hvB = ((const float4*)(myrow + 64))[r0];
                float4 gv = ((const float4*)sgl)[r0];
                float4 bv = ((const float4*)sbe)[r0];
#pragma unroll
                for (int r = 0; r < 4; r++) {
                    float hA1 = (r == 0) ? hvA.x : (r == 1) ? hvA.y : (r == 2) ? hvA.z : hvA.w;
                    float hB1 = (r == 0) ? hvB.x : (r == 1) ? hvB.y : (r == 2) ? hvB.z : hvB.w;
                    float gw1 = (r == 0) ? gv.x : (r == 1) ? gv.y : (r == 2) ? gv.z : gv.w;
                    float bw1 = (r == 0) ? bv.x : (r == 1) ? bv.y : (r == 2) ? bv.z : bv.w;
                    float aAv = fmaxf(fmaf((hA1 - mA) * ivA, gw1, bw1), 0.0f);
                    float aBv = fmaxf(fmaf((hB1 - mB) * ivB, gw1, bw1), 0.0f);
                    u64 aD = dup2(aAv);
                    u64 bD = dup2(aBv);
                    const ulonglong2* wr = (const ulonglong2*)(sW2 + (r0 * 4 + r) * 32);
#pragma unroll
                    for (int k = 0; k < 8; k++) {
                        ulonglong2 w = wr[k];
                        tA[2 * k]     = ffma2(aD, w.x, tA[2 * k]);
                        tA[2 * k + 1] = ffma2(aD, w.y, tA[2 * k + 1]);
                        tB[2 * k]     = ffma2(bD, w.x, tB[2 * k]);
                        tB[2 * k + 1] = ffma2(bD, w.y, tB[2 * k + 1]);
                    }
                }
            }
            {
                u64 nqA = mul2(tA[0], tA[0]);
                u64 nqB = mul2(tB[0], tB[0]);
#pragma unroll
                for (int k = 1; k < 16; k++) {
                    nqA = ffma2(tA[k], tA[k], nqA);
                    nqB = ffma2(tB[k], tB[k], nqB);
                }
                float2 fa = unpack2(nqA), fb = unpack2(nqB);
                u64 scA2 = dup2(sclA * rsqrtf(fmaxf(fa.x + fa.y, 1e-24f)));
                u64 scB2 = dup2(sclB * rsqrtf(fmaxf(fb.x + fb.y, 1e-24f)));
                float4* oA = (float4*)myrow;
                float4* oB = (float4*)(myrow + 64);
#pragma unroll
                for (int k = 0; k < 8; k++) {
                    float2 o0 = unpack2(mul2(tA[2 * k], scA2));
                    float2 o1 = unpack2(mul2(tA[2 * k + 1], scA2));
                    oA[k] = make_float4(o0.x, o0.y, o1.x, o1.y);
                    o0 = unpack2(mul2(tB[2 * k], scB2));
                    o1 = unpack2(mul2(tB[2 * k + 1], scB2));
                    oB[k] = make_float4(o0.x, o0.y, o1.x, o1.y);
                }
            }
            __syncwarp();

            for (int k = lane; k < 256; k += 32) {
                int m = k >> 3, j = k & 7;
                const float* src = wrows + m * K2_ROW;
                float4 vA = *(const float4*)(src + j * 4);
                float4 vB = *(const float4*)(src + 64 + j * 4);
                size_t rowA = (((size_t)(g * 64 + m) * 7 + line) * 3 + p) * 32;
                size_t rowB = (((size_t)(g * 64 + 32 + m) * 7 + line) * 3 + p) * 32;
                *(float4*)(out + rowA + j * 4) = vA;
                *(float4*)(out + rowB + j * 4) = vB;
            }
            __syncwarp();
        }
    }
}

// ============================================================================
extern "C" void kernel_launch(void* const* d_in, const int* in_sizes, int n_in,
                              void* d_out, int out_size)
{
    const float* z      = (const float*)d_in[0];
    const float* gen_W1 = (const float*)d_in[1];
    const float* gen_b1 = (const float*)d_in[2];
    const float* gen_g  = (const float*)d_in[3];
    const float* gen_be = (const float*)d_in[4];
    const float* gen_W2 = (const float*)d_in[5];
    const float* gen_b2 = (const float*)d_in[6];
    const float* cf_W1  = (const float*)d_in[7];
    const float* cf_b1  = (const float*)d_in[8];
    const float* cf_W2  = (const float*)d_in[9];
    const float* cf_b2  = (const float*)d_in[10];
    const float* g_W    = (const float*)d_in[11];
    const float* g_b    = (const float*)d_in[12];
    const float* c_W1   = (const float*)d_in[13];
    const float* c_b1   = (const float*)d_in[14];
    const float* c_g    = (const float*)d_in[15];
    const float* c_be   = (const float*)d_in[16];
    const float* c_W2   = (const float*)d_in[17];
    const float* c_b2   = (const float*)d_in[18];

    float* out      = (float*)d_out;                       // composed [B,7,3,32]
    float* out_conf = out + (size_t)B_TOTAL * 672;         // comp_conf [B,7,3]

    cudaFuncSetAttribute(colony_k1, cudaFuncAttributeMaxDynamicSharedMemorySize, K1_SMEM);
    cudaFuncSetAttribute(colony_k2, cudaFuncAttributeMaxDynamicSharedMemorySize, K2_SMEM);

    colony_k1<<<148, K1_THREADS, K1_SMEM>>>(z, gen_W1, gen_b1, gen_g, gen_be, gen_W2, gen_b2,
                                            cf_W1, cf_b1, cf_W2, cf_b2, g_W, g_b, out_conf);
    colony_k2<<<K2_GRID, K2_THREADS, K2_SMEM>>>(c_W1, c_b1, c_g, c_be, c_W2, c_b2, out);
}

// round 17
// speedup vs baseline: 1.3413x; 1.0620x over previous
#include <cuda_runtime.h>
#include <math.h>

#define B_TOTAL 65536
#define NBLK (B_TOTAL / 32)
#define NL 7

typedef unsigned long long u64;

// ---- scratch (static device globals) ----
__device__ __align__(16) float g_traces_blk[(size_t)B_TOTAL * 224];   // [blk][c][d][32]
__device__ __align__(16) float g_gates_T[(size_t)NL * B_TOTAL];       // [line][b]

__constant__ int FSRC[21] = {0,1,2, 0,3,4, 0,5,6, 1,3,5, 1,4,6, 2,3,6, 2,4,5};
__constant__ int FPAR[21] = {1,2,0, 3,4,0, 5,6,0, 3,5,1, 4,6,1, 3,6,2, 4,5,2};

__device__ __forceinline__ u64 pack2(float x, float y) {
    u64 r; asm("mov.b64 %0, {%1,%2};" : "=l"(r) : "f"(x), "f"(y)); return r;
}
__device__ __forceinline__ float2 unpack2(u64 v) {
    float2 r; asm("mov.b64 {%0,%1}, %2;" : "=f"(r.x), "=f"(r.y) : "l"(v)); return r;
}
__device__ __forceinline__ u64 dup2(float x) { return pack2(x, x); }
__device__ __forceinline__ u64 ffma2(u64 a, u64 b, u64 c) {
    u64 d; asm("fma.rn.f32x2 %0, %1, %2, %3;" : "=l"(d) : "l"(a), "l"(b), "l"(c)); return d;
}
__device__ __forceinline__ u64 add2(u64 a, u64 b) {
    u64 d; asm("add.rn.f32x2 %0, %1, %2;" : "=l"(d) : "l"(a), "l"(b)); return d;
}
__device__ __forceinline__ u64 mul2(u64 a, u64 b) {
    u64 d; asm("mul.rn.f32x2 %0, %1, %2;" : "=l"(d) : "l"(a), "l"(b)); return d;
}

__device__ __forceinline__ float fast_sigmoid(float x) {
    return __fdividef(1.0f, 1.0f + __expf(-x));
}

__device__ __forceinline__ float colony_act(int c, float x) {
    switch (c) {
        case 0: return fmaxf(x, 0.0f);
        case 1: { float e = __expf(2.0f * x); return 1.0f - __fdividef(2.0f, e + 1.0f); }
        case 2: return 0.5f * x * (1.0f + erff(x * 0.7071067811865476f));
        case 3: return x * fast_sigmoid(x);
        case 4: return fmaxf(x, 0.0f) + log1pf(__expf(-fabsf(x)));
        case 5: return fast_sigmoid(x);
        default: return fminf(fmaxf(x, -1.0f), 1.0f);
    }
}

// ============================================================================
// Kernel 1: lane = 2 batches (adjacent 32-blocks). Weight LDS shared across
// both batches (4 FFMA2 per LDS.128). Row = hA[64]|hB[64]|pad = 132 floats;
// z-transpose tile aliases the row region (h dead at colony start).
// ============================================================================
#define K1_WARPS 7
#define K1_THREADS (K1_WARPS * 32)
#define K1_ROW 132
#define K1_WSZ (27344 + K1_WARPS * 32 * K1_ROW)   // 56912 floats = 227648 B
#define K1_SMEM (K1_WSZ * 4)

__global__ void __launch_bounds__(K1_THREADS, 1)
colony_k1(const float* __restrict__ z,
          const float* __restrict__ gen_W1, const float* __restrict__ gen_b1,
          const float* __restrict__ gen_g,  const float* __restrict__ gen_be,
          const float* __restrict__ gen_W2, const float* __restrict__ gen_b2,
          const float* __restrict__ cf_W1,  const float* __restrict__ cf_b1,
          const float* __restrict__ cf_W2,  const float* __restrict__ cf_b2,
          const float* __restrict__ gw,     const float* __restrict__ gb,
          float* __restrict__ out_conf)
{
    extern __shared__ __align__(16) float sm[];
    float* sW1  = sm;            // 6272  [7][14][64]
    float* sb1  = sW1  + 6272;   // 448
    float* sg   = sb1  + 448;    // 448
    float* sbe  = sg   + 448;    // 448
    float* sW2  = sbe  + 448;    // 14336 [7][64][32]
    float* sb2  = sW2  + 14336;  // 224
    float* scW1 = sb2  + 224;    // 3136  [7][14][32]
    float* scb1 = scW1 + 3136;   // 224
    float* scW2 = scb1 + 224;    // 224
    float* scb2 = scW2 + 224;    // 8
    float* sgWT = scb2 + 8;      // 1568  transposed [7][224]
    float* sgb  = sgWT + 1568;   // 8
    float* rows = sgb  + 8;      // per-lane private rows [7][32][132]

    const int tid = threadIdx.x;
    for (int i = tid; i < 6272;  i += blockDim.x) sW1[i]  = gen_W1[i];
    for (int i = tid; i < 448;   i += blockDim.x) sb1[i]  = gen_b1[i];
    for (int i = tid; i < 448;   i += blockDim.x) sg[i]   = gen_g[i];
    for (int i = tid; i < 448;   i += blockDim.x) sbe[i]  = gen_be[i];
    for (int i = tid; i < 14336; i += blockDim.x) sW2[i]  = gen_W2[i];
    for (int i = tid; i < 224;   i += blockDim.x) sb2[i]  = gen_b2[i];
    for (int i = tid; i < 3136;  i += blockDim.x) scW1[i] = cf_W1[i];
    for (int i = tid; i < 224;   i += blockDim.x) scb1[i] = cf_b1[i];
    for (int i = tid; i < 224;   i += blockDim.x) scW2[i] = cf_W2[i];
    for (int i = tid; i < 7;     i += blockDim.x) scb2[i] = cf_b2[i];
    for (int i = tid; i < 1568;  i += blockDim.x) {
        int l = i / 224, d = i % 224;
        sgWT[i] = gw[d * 7 + l];
    }
    for (int i = tid; i < 7;     i += blockDim.x) sgb[i]  = gb[i];
    __syncthreads();

    const int wid  = tid >> 5;
    const int lane = tid & 31;
    float* wrows = rows + (wid * 32) * K1_ROW;
    float* myrow = wrows + lane * K1_ROW;     // hA [0,64) | hB [64,128)
    float* zt    = wrows;                     // transient 14x33 tile (aliases rows)

    const int gwarp = blockIdx.x * K1_WARPS + wid;
    const int nwarp = gridDim.x * K1_WARPS;
    const int ngroups = NBLK / 2;   // 1024

    for (int g = gwarp; g < ngroups; g += nwarp) {
        const int blkA = 2 * g, blkB = 2 * g + 1;
        const int bA = blkA * 32 + lane;
        const int bB = blkB * 32 + lane;
        u64 gaccA[7], gaccB[7];
        float cfA[7], cfB[7];
#pragma unroll
        for (int l = 0; l < 7; l++) { gaccA[l] = 0ull; gaccB[l] = 0ull; }

        for (int c = 0; c < NL; c++) {
            // ---- fused z transpose for both blocks (tile aliases rows; h dead) ----
            float xA[14], xB[14];
            {
                const float* zsrc = z + (size_t)blkA * 3136 + c * 14;
                __syncwarp();
#pragma unroll
                for (int k0 = 0; k0 < 14; k0++) {
                    int k = k0 * 32 + lane;
                    int m2 = k / 14, q = k - m2 * 14;
                    zt[q * 33 + m2] = zsrc[m2 * 98 + q];
                }
                __syncwarp();
#pragma unroll
                for (int q = 0; q < 14; q++) xA[q] = zt[q * 33 + lane];
                __syncwarp();
                const float* zsrcB = z + (size_t)blkB * 3136 + c * 14;
#pragma unroll
                for (int k0 = 0; k0 < 14; k0++) {
                    int k = k0 * 32 + lane;
                    int m2 = k / 14, q = k - m2 * 14;
                    zt[q * 33 + m2] = zsrcB[m2 * 98 + q];
                }
                __syncwarp();
#pragma unroll
                for (int q = 0; q < 14; q++) xB[q] = zt[q * 33 + lane];
                __syncwarp();
            }

            // ---- stage 1: h = x @ W1 + b1, two 32-col chunks, shared weights ----
            float s1A = 0.0f, s2A = 0.0f, s1B = 0.0f, s2B = 0.0f;
            for (int chunk = 0; chunk < 2; chunk++) {
                u64 hA[16], hB[16];
                {
                    const ulonglong2* bp = (const ulonglong2*)(sb1 + c * 64 + chunk * 32);
#pragma unroll
                    for (int k = 0; k < 8; k++) {
                        ulonglong2 bv = bp[k];
                        hA[2 * k] = bv.x; hA[2 * k + 1] = bv.y;
                        hB[2 * k] = bv.x; hB[2 * k + 1] = bv.y;
                    }
                }
                const float* Wb = sW1 + c * (14 * 64) + chunk * 32;
#pragma unroll
                for (int q = 0; q < 14; q++) {
                    u64 xdA = dup2(xA[q]);
                    u64 xdB = dup2(xB[q]);
                    const ulonglong2* wr = (const ulonglong2*)(Wb + q * 64);
#pragma unroll
                    for (int jj = 0; jj < 8; jj++) {
                        ulonglong2 w = wr[jj];
                        hA[2 * jj]     = ffma2(xdA, w.x, hA[2 * jj]);
                        hA[2 * jj + 1] = ffma2(xdA, w.y, hA[2 * jj + 1]);
                        hB[2 * jj]     = ffma2(xdB, w.x, hB[2 * jj]);
                        hB[2 * jj + 1] = ffma2(xdB, w.y, hB[2 * jj + 1]);
                    }
                }
                u64 spA = hA[0], qpA = mul2(hA[0], hA[0]);
                u64 spB = hB[0], qpB = mul2(hB[0], hB[0]);
#pragma unroll
                for (int k = 1; k < 16; k++) {
                    spA = add2(spA, hA[k]); qpA = ffma2(hA[k], hA[k], qpA);
                    spB = add2(spB, hB[k]); qpB = ffma2(hB[k], hB[k], qpB);
                }
                float2 fsA = unpack2(spA), fqA = unpack2(qpA);
                float2 fsB = unpack2(spB), fqB = unpack2(qpB);
                s1A += fsA.x + fsA.y;  s2A += fqA.x + fqA.y;
                s1B += fsB.x + fsB.y;  s2B += fqB.x + fqB.y;
                float4* hstA = (float4*)(myrow + chunk * 32);
                float4* hstB = (float4*)(myrow + 64 + chunk * 32);
#pragma unroll
                for (int k = 0; k < 8; k++) {
                    float2 lo = unpack2(hA[2 * k]);
                    float2 hi = unpack2(hA[2 * k + 1]);
                    hstA[k] = make_float4(lo.x, lo.y, hi.x, hi.y);
                    lo = unpack2(hB[2 * k]);
                    hi = unpack2(hB[2 * k + 1]);
                    hstB[k] = make_float4(lo.x, lo.y, hi.x, hi.y);
                }
            }
            const float mA = s1A * (1.0f / 64.0f);
            const float mB = s1B * (1.0f / 64.0f);
            const float ivA = rsqrtf(fmaxf(s2A * (1.0f / 64.0f) - mA * mA, 0.0f) + 1e-5f);
            const float ivB = rsqrtf(fmaxf(s2B * (1.0f / 64.0f) - mB * mB, 0.0f) + 1e-5f);

            // ---- stage 2: t = ACT(LN(h)) @ W2 + b2 (fused, shared weights) ----
            u64 tA[16], tB[16];
            {
                const ulonglong2* bp = (const ulonglong2*)(sb2 + c * 32);
#pragma unroll
                for (int k = 0; k < 8; k++) {
                    ulonglong2 bv = bp[k];
                    tA[2 * k] = bv.x; tA[2 * k + 1] = bv.y;
                    tB[2 * k] = bv.x; tB[2 * k + 1] = bv.y;
                }
            }
            for (int r0 = 0; r0 < 16; r0++) {
                float4 hvA = ((const float4*)myrow)[r0];
                float4 hvB = ((const float4*)(myrow + 64))[r0];
                float4 gv = *(const float4*)(sg + c * 64 + r0 * 4);
                float4 bv = *(const float4*)(sbe + c * 64 + r0 * 4);
#pragma unroll
                for (int r = 0; r < 4; r++) {
                    float hhA = (r == 0) ? hvA.x : (r == 1) ? hvA.y : (r == 2) ? hvA.z : hvA.w;
                    float hhB = (r == 0) ? hvB.x : (r == 1) ? hvB.y : (r == 2) ? hvB.z : hvB.w;
                    float gg = (r == 0) ? gv.x : (r == 1) ? gv.y : (r == 2) ? gv.z : gv.w;
                    float bb = (r == 0) ? bv.x : (r == 1) ? bv.y : (r == 2) ? bv.z : bv.w;
                    float avA = colony_act(c, fmaf((hhA - mA) * ivA, gg, bb));
                    float avB = colony_act(c, fmaf((hhB - mB) * ivB, gg, bb));
                    u64 adA = dup2(avA);
                    u64 adB = dup2(avB);
                    const ulonglong2* wr = (const ulonglong2*)(sW2 + c * 2048 + (r0 * 4 + r) * 32);
#pragma unroll
                    for (int k = 0; k < 8; k++) {
                        ulonglong2 w = wr[k];
                        tA[2 * k]     = ffma2(adA, w.x, tA[2 * k]);
                        tA[2 * k + 1] = ffma2(adA, w.y, tA[2 * k + 1]);
                        tB[2 * k]     = ffma2(adB, w.x, tB[2 * k]);
                        tB[2 * k + 1] = ffma2(adB, w.y, tB[2 * k + 1]);
                    }
                }
            }
            // ---- l2norm ----
            {
                u64 nqA = mul2(tA[0], tA[0]);
                u64 nqB = mul2(tB[0], tB[0]);
#pragma unroll
                for (int k = 1; k < 16; k++) {
                    nqA = ffma2(tA[k], tA[k], nqA);
                    nqB = ffma2(tB[k], tB[k], nqB);
                }
                float2 nfA = unpack2(nqA), nfB = unpack2(nqB);
                u64 ndA = dup2(rsqrtf(fmaxf(nfA.x + nfA.y, 1e-24f)));
                u64 ndB = dup2(rsqrtf(fmaxf(nfB.x + nfB.y, 1e-24f)));
#pragma unroll
                for (int k = 0; k < 16; k++) {
                    tA[k] = mul2(tA[k], ndA);
                    tB[k] = mul2(tB[k], ndB);
                }
            }

            // ---- store blocked traces (coalesced STG.32 per dim, both blocks) ----
            {
                float* tbA = g_traces_blk + (size_t)blkA * 7168 + c * 1024 + lane;
                float* tbB = g_traces_blk + (size_t)blkB * 7168 + c * 1024 + lane;
#pragma unroll
                for (int k = 0; k < 16; k++) {
                    float2 fA = unpack2(tA[k]);
                    float2 fB = unpack2(tB[k]);
                    tbA[(2 * k) * 32]     = fA.x;
                    tbA[(2 * k + 1) * 32] = fA.y;
                    tbB[(2 * k) * 32]     = fB.x;
                    tbB[(2 * k + 1) * 32] = fB.y;
                }
            }
            // ---- accumulate gates (shared weight loads) ----
#pragma unroll
            for (int l = 0; l < 7; l++) {
                const ulonglong2* gp = (const ulonglong2*)(sgWT + l * 224 + c * 32);
                u64 accA = gaccA[l];
                u64 accB = gaccB[l];
#pragma unroll
                for (int k = 0; k < 8; k++) {
                    ulonglong2 w = gp[k];
                    accA = ffma2(tA[2 * k], w.x, accA);
                    accA = ffma2(tA[2 * k + 1], w.y, accA);
                    accB = ffma2(tB[2 * k], w.x, accB);
                    accB = ffma2(tB[2 * k + 1], w.y, accB);
                }
                gaccA[l] = accA;
                gaccB[l] = accB;
            }
            // ---- confidence head (shared weight loads) ----
            {
                u64 hcA[16], hcB[16];
                const ulonglong2* bp = (const ulonglong2*)(scb1 + c * 32);
#pragma unroll
                for (int k = 0; k < 8; k++) {
                    ulonglong2 bv = bp[k];
                    hcA[2 * k] = bv.x; hcA[2 * k + 1] = bv.y;
                    hcB[2 * k] = bv.x; hcB[2 * k + 1] = bv.y;
                }
                const float* cw = scW1 + c * 448;
#pragma unroll
                for (int q = 0; q < 14; q++) {
                    u64 xdA = dup2(xA[q]);
                    u64 xdB = dup2(xB[q]);
                    const ulonglong2* wr = (const ulonglong2*)(cw + q * 32);
#pragma unroll
                    for (int k = 0; k < 8; k++) {
                        ulonglong2 w = wr[k];
                        hcA[2 * k]     = ffma2(xdA, w.x, hcA[2 * k]);
                        hcA[2 * k + 1] = ffma2(xdA, w.y, hcA[2 * k + 1]);
                        hcB[2 * k]     = ffma2(xdB, w.x, hcB[2 * k]);
                        hcB[2 * k + 1] = ffma2(xdB, w.y, hcB[2 * k + 1]);
                    }
                }
                float daccA = 0.0f, daccB = 0.0f;
                const u64* w2p = (const u64*)(scW2 + c * 32);
#pragma unroll
                for (int k = 0; k < 16; k++) {
                    float2 ww = unpack2(w2p[k]);
                    float2 hhA = unpack2(hcA[k]);
                    float2 hhB = unpack2(hcB[k]);
                    daccA = fmaf(fmaxf(hhA.x, 0.0f), ww.x, daccA);
                    daccA = fmaf(fmaxf(hhA.y, 0.0f), ww.y, daccA);
                    daccB = fmaf(fmaxf(hhB.x, 0.0f), ww.x, daccB);
                    daccB = fmaf(fmaxf(hhB.y, 0.0f), ww.y, daccB);
                }
                cfA[c] = fast_sigmoid(daccA + scb2[c]);
                cfB[c] = fast_sigmoid(daccB + scb2[c]);
            }
        }

        // ---- gates final + stores ----
        float gateA[7], gateB[7];
#pragma unroll
        for (int l = 0; l < 7; l++) {
            float2 fA = unpack2(gaccA[l]);
            float2 fB = unpack2(gaccB[l]);
            gateA[l] = fast_sigmoid(fA.x + fA.y + sgb[l]);
            gateB[l] = fast_sigmoid(fB.x + fB.y + sgb[l]);
            g_gates_T[(size_t)l * B_TOTAL + bA] = gateA[l];
            g_gates_T[(size_t)l * B_TOTAL + bB] = gateB[l];
        }
#pragma unroll
        for (int j = 0; j < 21; j++) {
            float glA = gateA[j / 3];
            float glB = gateB[j / 3];
            out_conf[(size_t)bA * 21 + j] = (glA >= 0.3f) ? cfA[FSRC[j]] * cfA[FPAR[j]] * glA : 0.0f;
            out_conf[(size_t)bB * 21 + j] = (glB >= 0.3f) ? cfB[FSRC[j]] * cfB[FPAR[j]] * glB : 0.0f;
        }
    }
}

// ============================================================================
// Kernel 2: EXACT round-12/16 version (10 warps, row 132) — proven ~430us.
// ============================================================================
#define K2_WARPS 10
#define K2_THREADS (K2_WARPS * 32)
#define K2_BLK_PER_LINE 21
#define K2_GRID (NL * K2_BLK_PER_LINE)
#define K2_ROW 132
#define K2_WSZ (6368 + K2_WARPS * 32 * K2_ROW)
#define K2_SMEM (K2_WSZ * 4)

__global__ void __launch_bounds__(K2_THREADS, 1)
colony_k2(const float* __restrict__ cW1, const float* __restrict__ cb1,
          const float* __restrict__ cg,  const float* __restrict__ cbe,
          const float* __restrict__ cW2, const float* __restrict__ cb2,
          float* __restrict__ out)
{
    extern __shared__ __align__(16) float sm[];
    float* sW1 = sm;
    float* sW2 = sW1 + 4096;
    float* sb1 = sW2 + 2048;
    float* sgl = sb1 + 64;
    float* sbe = sgl + 64;
    float* sb2 = sbe + 64;
    float* stile = sb2 + 32;

    const int line = blockIdx.x % NL;
    const int tid = threadIdx.x;
    {
        const float* w1 = cW1 + line * 4096;
        const float* w2 = cW2 + line * 2048;
        for (int i = tid; i < 4096; i += blockDim.x) sW1[i] = w1[i];
        for (int i = tid; i < 2048; i += blockDim.x) sW2[i] = w2[i];
        if (tid < 64) {
            sb1[tid] = cb1[line * 64 + tid];
            sgl[tid] = cg[line * 64 + tid];
            sbe[tid] = cbe[line * 64 + tid];
        }
        if (tid < 32) sb2[tid] = cb2[line * 32 + tid];
    }
    __syncthreads();

    const int wid  = tid >> 5;
    const int lane = tid & 31;
    float* myrow = stile + (wid * 32 + lane) * K2_ROW;
    float* wrows = stile + (wid * 32) * K2_ROW;

    const int col0 = FSRC[line * 3 + 0];
    const int col1 = FSRC[line * 3 + 1];
    const int col2 = FSRC[line * 3 + 2];

    const int lwarp = (blockIdx.x / NL) * K2_WARPS + wid;
    const int nlw   = K2_BLK_PER_LINE * K2_WARPS;
    const int ngroups = B_TOTAL / 64;

    for (int g = lwarp; g < ngroups; g += nlw) {
        const int blkA = 2 * g, blkB = 2 * g + 1;
        const int bA = g * 64 + lane;
        const int bB = bA + 32;

        const float gateA = g_gates_T[(size_t)line * B_TOTAL + bA];
        const float gateB = g_gates_T[(size_t)line * B_TOTAL + bB];
        const float sclA = (gateA >= 0.3f) ? gateA : 0.0f;
        const float sclB = (gateB >= 0.3f) ? gateB : 0.0f;

        for (int p = 0; p < 3; p++) {
            const int cS = (p == 0) ? col0 : (p == 1) ? col1 : col2;
            const int cP = (p == 0) ? col1 : (p == 1) ? col2 : col0;

            float s1A = 0.0f, s2A = 0.0f, s1B = 0.0f, s2B = 0.0f;
            for (int chunk = 0; chunk < 2; chunk++) {
                u64 hA[16], hB[16];
                {
                    const ulonglong2* bp = (const ulonglong2*)(sb1 + chunk * 32);
#pragma unroll
                    for (int k = 0; k < 8; k++) {
                        ulonglong2 bv = bp[k];
                        hA[2 * k] = bv.x; hA[2 * k + 1] = bv.y;
                        hB[2 * k] = bv.x; hB[2 * k + 1] = bv.y;
                    }
                }
                for (int half = 0; half < 2; half++) {
                    const int colony = half ? cP : cS;
                    const float* xA = g_traces_blk + (size_t)blkA * 7168 + colony * 1024 + lane;
                    const float* xB = g_traces_blk + (size_t)blkB * 7168 + colony * 1024 + lane;
                    const float* Wb = sW1 + half * 2048 + chunk * 32;
#pragma unroll 8
                    for (int i = 0; i < 32; i++) {
                        u64 aD = dup2(xA[i * 32]);
                        u64 bD = dup2(xB[i * 32]);
                        const ulonglong2* wr = (const ulonglong2*)(Wb + i * 64);
#pragma unroll
                        for (int jj = 0; jj < 8; jj++) {
                            ulonglong2 w = wr[jj];
                            hA[2 * jj]     = ffma2(aD, w.x, hA[2 * jj]);
                            hA[2 * jj + 1] = ffma2(aD, w.y, hA[2 * jj + 1]);
                            hB[2 * jj]     = ffma2(bD, w.x, hB[2 * jj]);
                            hB[2 * jj + 1] = ffma2(bD, w.y, hB[2 * jj + 1]);
                        }
                    }
                }
                {
                    u64 sAp = hA[0], qAp = mul2(hA[0], hA[0]);
                    u64 sBp = hB[0], qBp = mul2(hB[0], hB[0]);
#pragma unroll
                    for (int k = 1; k < 16; k++) {
                        sAp = add2(sAp, hA[k]); qAp = ffma2(hA[k], hA[k], qAp);
                        sBp = add2(sBp, hB[k]); qBp = ffma2(hB[k], hB[k], qBp);
                    }
                    float2 a1 = unpack2(sAp), a2 = unpack2(qAp);
                    float2 b1 = unpack2(sBp), b2 = unpack2(qBp);
                    s1A += a1.x + a1.y;  s2A += a2.x + a2.y;
                    s1B += b1.x + b1.y;  s2B += b2.x + b2.y;
                }
                {
                    float4* hstA = (float4*)(myrow + chunk * 32);
                    float4* hstB = (float4*)(myrow + 64 + chunk * 32);
#pragma unroll
                    for (int k = 0; k < 8; k++) {
                        float2 lo = unpack2(hA[2 * k]);
                        float2 hi = unpack2(hA[2 * k + 1]);
                        hstA[k] = make_float4(lo.x, lo.y, hi.x, hi.y);
                        lo = unpack2(hB[2 * k]);
                        hi = unpack2(hB[2 * k + 1]);
                        hstB[k] = make_float4(lo.x, lo.y, hi.x, hi.y);
                    }
                }
            }
            const float mA = s1A * (1.0f / 64.0f);
            const float mB = s1B * (1.0f / 64.0f);
            const float ivA = rsqrtf(fmaxf(s2A * (1.0f / 64.0f) - mA * mA, 0.0f) + 1e-5f);
            const float ivB = rsqrtf(fmaxf(s2B * (1.0f / 64.0f) - mB * mB, 0.0f) + 1e-5f);

            u64 tA[16], tB[16];
            {
                const ulonglong2* bp = (const ulonglong2*)sb2;
#pragma unroll
                for (int k = 0; k < 8; k++) {
                    ulonglong2 bv = bp[k];
                    tA[2 * k] = bv.x; tA[2 * k + 1] = bv.y;
                    tB[2 * k] = bv.x; tB[2 * k + 1] = bv.y;
                }
            }
#pragma unroll 4
            for (int r0 = 0; r0 < 16; r0++) {
                float4 hvA = ((const float4*)myrow)[r0];
                float4 hvB = ((const float4*)(myrow + 64))[r0];
                float4 gv = ((const float4*)sgl)[r0];
                float4 bv = ((const float4*)sbe)[r0];
#pragma unroll
                for (int r = 0; r < 4; r++) {
                    float hA1 = (r == 0) ? hvA.x : (r == 1) ? hvA.y : (r == 2) ? hvA.z : hvA.w;
                    float hB1 = (r == 0) ? hvB.x : (r == 1) ? hvB.y : (r == 2) ? hvB.z : hvB.w;
                    float gw1 = (r == 0) ? gv.x : (r == 1) ? gv.y : (r == 2) ? gv.z : gv.w;
                    float bw1 = (r == 0) ? bv.x : (r == 1) ? bv.y : (r == 2) ? bv.z : bv.w;
                    float aAv = fmaxf(fmaf((hA1 - mA) * ivA, gw1, bw1), 0.0f);
                    float aBv = fmaxf(fmaf((hB1 - mB) * ivB, gw1, bw1), 0.0f);
                    u64 aD = dup2(aAv);
                    u64 bD = dup2(aBv);
                    const ulonglong2* wr = (const ulonglong2*)(sW2 + (r0 * 4 + r) * 32);
#pragma unroll
                    for (int k = 0; k < 8; k++) {
                        ulonglong2 w = wr[k];
                        tA[2 * k]     = ffma2(aD, w.x, tA[2 * k]);
                        tA[2 * k + 1] = ffma2(aD, w.y, tA[2 * k + 1]);
                        tB[2 * k]     = ffma2(bD, w.x, tB[2 * k]);
                        tB[2 * k + 1] = ffma2(bD, w.y, tB[2 * k + 1]);
                    }
                }
            }
            {
                u64 nqA = mul2(tA[0], tA[0]);
                u64 nqB = mul2(tB[0], tB[0]);
#pragma unroll
                for (int k = 1; k < 16; k++) {
                    nqA = ffma2(tA[k], tA[k], nqA);
                    nqB = ffma2(tB[k], tB[k], nqB);
                }
                float2 fa = unpack2(nqA), fb = unpack2(nqB);
                u64 scA2 = dup2(sclA * rsqrtf(fmaxf(fa.x + fa.y, 1e-24f)));
                u64 scB2 = dup2(sclB * rsqrtf(fmaxf(fb.x + fb.y, 1e-24f)));
                float4* oA = (float4*)myrow;
                float4* oB = (float4*)(myrow + 64);
#pragma unroll
                for (int k = 0; k < 8; k++) {
                    float2 o0 = unpack2(mul2(tA[2 * k], scA2));
                    float2 o1 = unpack2(mul2(tA[2 * k + 1], scA2));
                    oA[k] = make_float4(o0.x, o0.y, o1.x, o1.y);
                    o0 = unpack2(mul2(tB[2 * k], scB2));
                    o1 = unpack2(mul2(tB[2 * k + 1], scB2));
                    oB[k] = make_float4(o0.x, o0.y, o1.x, o1.y);
                }
            }
            __syncwarp();

            for (int k = lane; k < 256; k += 32) {
                int m = k >> 3, j = k & 7;
                const float* src = wrows + m * K2_ROW;
                float4 vA = *(const float4*)(src + j * 4);
                float4 vB = *(const float4*)(src + 64 + j * 4);
                size_t rowA = (((size_t)(g * 64 + m) * 7 + line) * 3 + p) * 32;
                size_t rowB = (((size_t)(g * 64 + 32 + m) * 7 + line) * 3 + p) * 32;
                *(float4*)(out + rowA + j * 4) = vA;
                *(float4*)(out + rowB + j * 4) = vB;
            }
            __syncwarp();
        }
    }
}

// ============================================================================
extern "C" void kernel_launch(void* const* d_in, const int* in_sizes, int n_in,
                              void* d_out, int out_size)
{
    const float* z      = (const float*)d_in[0];
    const float* gen_W1 = (const float*)d_in[1];
    const float* gen_b1 = (const float*)d_in[2];
    const float* gen_g  = (const float*)d_in[3];
    const float* gen_be = (const float*)d_in[4];
    const float* gen_W2 = (const float*)d_in[5];
    const float* gen_b2 = (const float*)d_in[6];
    const float* cf_W1  = (const float*)d_in[7];
    const float* cf_b1  = (const float*)d_in[8];
    const float* cf_W2  = (const float*)d_in[9];
    const float* cf_b2  = (const float*)d_in[10];
    const float* g_W    = (const float*)d_in[11];
    const float* g_b    = (const float*)d_in[12];
    const float* c_W1   = (const float*)d_in[13];
    const float* c_b1   = (const float*)d_in[14];
    const float* c_g    = (const float*)d_in[15];
    const float* c_be   = (const float*)d_in[16];
    const float* c_W2   = (const float*)d_in[17];
    const float* c_b2   = (const float*)d_in[18];

    float* out      = (float*)d_out;                       // composed [B,7,3,32]
    float* out_conf = out + (size_t)B_TOTAL * 672;         // comp_conf [B,7,3]

    cudaFuncSetAttribute(colony_k1, cudaFuncAttributeMaxDynamicSharedMemorySize, K1_SMEM);
    cudaFuncSetAttribute(colony_k2, cudaFuncAttributeMaxDynamicSharedMemorySize, K2_SMEM);

    colony_k1<<<148, K1_THREADS, K1_SMEM>>>(z, gen_W1, gen_b1, gen_g, gen_be, gen_W2, gen_b2,
                                            cf_W1, cf_b1, cf_W2, cf_b2, g_W, g_b, out_conf);
    colony_k2<<<K2_GRID, K2_THREADS, K2_SMEM>>>(c_W1, c_b1, c_g, c_be, c_W2, c_b2, out);
}